// round 6
// baseline (speedup 1.0000x reference)
#include <cuda_runtime.h>
#include <math.h>

// Problem sizes (fixed by the reference)
#define TT 512
#define BB 128
#define HH 512
#define H3 1536

// ---------------- scratch (static __device__, no allocs) ----------------
__device__ float g_GI[TT * BB * H3];       // precomputed x@Wi + bi
__device__ float g_Ht[2 * HH * BB];        // TRANSPOSED hidden state [buf][j][b], reset pre-applied
__device__ float g_RS[(TT + 1) * BB];      // keep multipliers: 0 = reset, 1 = keep (row TT = 1)
__device__ int   g_reset_mode;             // 0=int32, 1=byte, 2=float32
__device__ unsigned int g_count;           // grid barrier arrive counter
__device__ unsigned int g_gen;             // grid barrier generation

// ---------------- f32x2 packed-FMA helpers (FFMA2) ----------------
__device__ __forceinline__ unsigned long long pack2(float lo, float hi) {
    unsigned long long r;
    asm("mov.b64 %0, {%1, %2};" : "=l"(r) : "f"(lo), "f"(hi));
    return r;
}
__device__ __forceinline__ float2 unpack2(unsigned long long v) {
    float2 f;
    asm("mov.b64 {%0, %1}, %2;" : "=f"(f.x), "=f"(f.y) : "l"(v));
    return f;
}
__device__ __forceinline__ void fma2(unsigned long long& d,
                                     unsigned long long a, unsigned long long b) {
    asm("fma.rn.f32x2 %0, %1, %2, %0;" : "+l"(d) : "l"(a), "l"(b));
}
// 16B async copy gmem -> smem (L1 bypass)
__device__ __forceinline__ void cp16(void* dst, const void* src) {
    unsigned s = (unsigned)__cvta_generic_to_shared(dst);
    asm volatile("cp.async.cg.shared.global [%0], [%1], 16;" :: "r"(s), "l"(src));
}

// ---------------- detect how the harness stored the bool resets ----------
__global__ void detect_reset_mode_kernel(const unsigned char* __restrict__ r) {
    __shared__ int cnt[4];
    if (threadIdx.x < 4) cnt[threadIdx.x] = 0;
    __syncthreads();
    int local[4] = {0, 0, 0, 0};
    const uchar4* r4 = (const uchar4*)r;
    for (int i = threadIdx.x; i < (TT * BB) / 4; i += blockDim.x) {
        uchar4 v = r4[i];
        local[0] += (v.x != 0); local[1] += (v.y != 0);
        local[2] += (v.z != 0); local[3] += (v.w != 0);
    }
#pragma unroll
    for (int q = 0; q < 4; ++q) atomicAdd(&cnt[q], local[q]);
    __syncthreads();
    if (threadIdx.x == 0) {
        int mode;
        if (cnt[1] > 0) mode = 1;                       // dense byte bools
        else if (cnt[0] > 0) mode = 0;                  // little-endian int32 0/1
        else if (cnt[2] > 0 || cnt[3] > 0) mode = 2;    // float32 0.0/1.0
        else mode = 0;
        g_reset_mode = mode;
    }
}

// ---------------- expand resets into fp32 keep-multipliers ----------------
__global__ void expand_resets_kernel(const void* __restrict__ resets) {
    int i = blockIdx.x * blockDim.x + threadIdx.x;
    if (i >= (TT + 1) * BB) return;
    if (i >= TT * BB) { g_RS[i] = 1.0f; return; }
    const int mode = g_reset_mode;
    bool rst;
    if (mode == 0)      rst = ((const int*)resets)[i] != 0;
    else if (mode == 1) rst = ((const unsigned char*)resets)[i] != 0;
    else                rst = ((const float*)resets)[i] != 0.0f;
    g_RS[i] = rst ? 0.0f : 1.0f;
}

// ---------------- init: reset barrier, load transposed h0 with keep(0) ----
__global__ void init_kernel(const float* __restrict__ h0) {
    int i = blockIdx.x * blockDim.x + threadIdx.x;
    if (i == 0) { g_count = 0u; g_gen = 0u; }
    if (i < BB * HH) {
        int b = i >> 9;          // / HH
        int j = i & (HH - 1);
        g_Ht[j * BB + b] = h0[i] * g_RS[b];
    }
}

// ---------------- GI GEMM: [65536,512] @ [512,1536] + bias (FFMA2) --------
#define GM 128
#define GN 128
#define GK 16

__global__ __launch_bounds__(256) void gi_gemm_kernel(
    const float* __restrict__ A,     // x as [T*B, H]
    const float* __restrict__ Bm,    // Wi [H, 3H]
    const float* __restrict__ bias)  // bi [3H]
{
    __shared__ float As[GK][GM];        // transposed A tile
    __shared__ float Bs[GK][GN + 4];    // padded B tile

    const int n0 = blockIdx.x * GN;
    const int m0 = blockIdx.y * GM;
    const int tid = threadIdx.x;
    const int tx = tid & 15;   // n direction
    const int ty = tid >> 4;   // m direction

    // acc pairs along n: acc2[i][jp] holds columns (2jp, 2jp+1)
    unsigned long long acc2[8][4];
#pragma unroll
    for (int i = 0; i < 8; ++i)
#pragma unroll
        for (int jp = 0; jp < 4; ++jp) acc2[i][jp] = 0ull;

    for (int k0 = 0; k0 < HH; k0 += GK) {
        // load A tile (128 rows x 16 k) as float4, store transposed
#pragma unroll
        for (int i = 0; i < 2; ++i) {
            int id = tid * 2 + i;            // 0..511
            int row = id >> 2;
            int c4 = id & 3;
            float4 v = *(const float4*)(A + (size_t)(m0 + row) * HH + k0 + c4 * 4);
            As[c4 * 4 + 0][row] = v.x;
            As[c4 * 4 + 1][row] = v.y;
            As[c4 * 4 + 2][row] = v.z;
            As[c4 * 4 + 3][row] = v.w;
        }
        // load B tile (16 k x 128 n)
#pragma unroll
        for (int i = 0; i < 2; ++i) {
            int id = tid * 2 + i;            // 0..511
            int kr = id >> 5;                // 0..15
            int n4 = id & 31;
            float4 v = *(const float4*)(Bm + (size_t)(k0 + kr) * H3 + n0 + n4 * 4);
            *(float4*)&Bs[kr][n4 * 4] = v;
        }
        __syncthreads();

#pragma unroll 8
        for (int kk = 0; kk < GK; ++kk) {
            float a[8];
            *(float4*)&a[0] = *(const float4*)&As[kk][ty * 8];
            *(float4*)&a[4] = *(const float4*)&As[kk][ty * 8 + 4];
            const ulonglong2 b01 = *(const ulonglong2*)&Bs[kk][tx * 8];
            const ulonglong2 b23 = *(const ulonglong2*)&Bs[kk][tx * 8 + 4];
#pragma unroll
            for (int i = 0; i < 8; ++i) {
                unsigned long long ai = pack2(a[i], a[i]);
                fma2(acc2[i][0], ai, b01.x);
                fma2(acc2[i][1], ai, b01.y);
                fma2(acc2[i][2], ai, b23.x);
                fma2(acc2[i][3], ai, b23.y);
            }
        }
        __syncthreads();
    }

    // epilogue: add bias, store
    float bb[8];
#pragma unroll
    for (int q = 0; q < 8; ++q) bb[q] = bias[n0 + tx * 8 + q];

#pragma unroll
    for (int i = 0; i < 8; ++i) {
        int m = m0 + ty * 8 + i;
        float* dst = g_GI + (size_t)m * H3 + n0 + tx * 8;
        float2 p0 = unpack2(acc2[i][0]);
        float2 p1 = unpack2(acc2[i][1]);
        float2 p2 = unpack2(acc2[i][2]);
        float2 p3 = unpack2(acc2[i][3]);
        float4 o0, o1;
        o0.x = p0.x + bb[0]; o0.y = p0.y + bb[1];
        o0.z = p1.x + bb[2]; o0.w = p1.y + bb[3];
        o1.x = p2.x + bb[4]; o1.y = p2.y + bb[5];
        o1.z = p3.x + bb[6]; o1.w = p3.y + bb[7];
        *(float4*)(dst + 0) = o0;
        *(float4*)(dst + 4) = o1;
    }
}

// ---------------- persistent scan kernel ----------------
#define NCTA 128
#define SCAN_THREADS 128

// smem layout (floats):
//   sWh  [512][12]          6144   (24KB) : this CTA's 12 gate-cols, [k][c], c = hcol*3+g
//   sHT  [2][128][128]     32768  (128KB) : double-buffered h^T chunks [k_local][b]
//   sGI  [3][128][4]        1536    (6KB) : staged gi slice for this step
//   sRed [4][32][52]        6656   (26KB) : per-warp partial sums (pad 52 vs 48)
#define SWH_OFF  0
#define SHT_OFF  6144
#define SGI_OFF  (6144 + 32768)
#define SRED_OFF (6144 + 32768 + 1536)
#define SCAN_SMEM_FLOATS (6144 + 32768 + 1536 + 6656)
#define SCAN_SMEM_BYTES (SCAN_SMEM_FLOATS * 4)

__device__ __forceinline__ void grid_sync(unsigned int nctas, unsigned int& gen) {
    __syncthreads();
    if (threadIdx.x == 0) {
        __threadfence();
        unsigned int prev = atomicAdd(&g_count, 1u);
        if (prev == nctas - 1u) {
            atomicExch(&g_count, 0u);
            __threadfence();
            atomicAdd(&g_gen, 1u);
        } else {
            unsigned int cur;
            do {
                asm volatile("ld.acquire.gpu.u32 %0, [%1];"
                             : "=r"(cur) : "l"(&g_gen) : "memory");
            } while (cur == gen);
        }
    }
    gen++;
    __syncthreads();
}

extern __shared__ float smf[];

__global__ __launch_bounds__(SCAN_THREADS, 1) void scan_kernel(
    const float* __restrict__ Wh,              // [H, 3H]
    const float* __restrict__ bhn,             // [H]
    float* __restrict__ out)                   // [T,B,H]
{
    float* sWh  = smf + SWH_OFF;
    float* sHT  = smf + SHT_OFF;
    float* sGI  = smf + SGI_OFF;
    float* sRed = smf + SRED_OFF;

    const int tid  = threadIdx.x;
    const int lane = tid & 31;
    const int wid  = tid >> 5;             // warp = k-slice owner AND epilogue col group
    const int jbase = blockIdx.x * 4;
    const int cj = jbase >> 7;             // chunk containing this CTA's h-columns
    const int cg = wid;
    const int j = jbase + cg;
    const float bhn_j = bhn[j];

    // load this CTA's 12 Wh gate-columns once: sWh[k*12 + c], c = hcol*3 + g
    for (int p = tid; p < 6144; p += SCAN_THREADS) {
        int k = p / 12, c = p % 12;
        sWh[p] = Wh[(size_t)k * H3 + (c % 3) * HH + jbase + c / 3];
    }
    __syncthreads();

    unsigned int gen = 0;

    for (int t = 0; t < TT; ++t) {
        const float* hsrc = g_Ht + (t & 1) * HH * BB;          // h^T, reset applied
        float* hdst       = g_Ht + ((t + 1) & 1) * HH * BB;
        const float* gi   = g_GI + (size_t)t * BB * H3;

        // stage chunk 0 (h^T rows 0..127) + gi slice  -> commit group
#pragma unroll
        for (int q = 0; q < 32; ++q) {
            int p = tid + q * SCAN_THREADS;
            int kr = p >> 5, c4 = p & 31;
            cp16(sHT + kr * 128 + c4 * 4, hsrc + (size_t)kr * BB + c4 * 4);
        }
#pragma unroll
        for (int g = 0; g < 3; ++g)
            cp16(sGI + (g * 128 + tid) * 4, gi + (size_t)tid * H3 + g * HH + jbase);
        asm volatile("cp.async.commit_group;");

        // per-warp k-slice accumulators: rows b = 4*lane + r, col-pairs (2p,2p+1)
        unsigned long long acc[4][6];
#pragma unroll
        for (int r = 0; r < 4; ++r)
#pragma unroll
            for (int p = 0; p < 6; ++p) acc[r][p] = 0ull;

        float hv[4];

        for (int c = 0; c < 4; ++c) {
            if (c < 3) {
                float* dstb = sHT + ((c + 1) & 1) * 16384;
#pragma unroll
                for (int q = 0; q < 32; ++q) {
                    int p = tid + q * SCAN_THREADS;
                    int kr = p >> 5, c4 = p & 31;
                    cp16(dstb + kr * 128 + c4 * 4,
                         hsrc + (size_t)((c + 1) * 128 + kr) * BB + c4 * 4);
                }
                asm volatile("cp.async.commit_group;");
                asm volatile("cp.async.wait_group 1;");
            } else {
                asm volatile("cp.async.wait_group 0;");
            }
            __syncthreads();

            const float* hb = sHT + (c & 1) * 16384;
            const float* hw = hb + (wid * 32) * 128;                 // warp's k rows
            const float* ww = sWh + (c * 128 + wid * 32) * 12;       // matching weights

#pragma unroll 4
            for (int kk = 0; kk < 32; ++kk) {
                const float4 h4 = *(const float4*)(hw + kk * 128 + lane * 4);
                const ulonglong2 wA = *(const ulonglong2*)(ww + kk * 12);
                const ulonglong2 wB = *(const ulonglong2*)(ww + kk * 12 + 4);
                const ulonglong2 wC = *(const ulonglong2*)(ww + kk * 12 + 8);
                unsigned long long hp;
                hp = pack2(h4.x, h4.x);
                fma2(acc[0][0], hp, wA.x); fma2(acc[0][1], hp, wA.y);
                fma2(acc[0][2], hp, wB.x); fma2(acc[0][3], hp, wB.y);
                fma2(acc[0][4], hp, wC.x); fma2(acc[0][5], hp, wC.y);
                hp = pack2(h4.y, h4.y);
                fma2(acc[1][0], hp, wA.x); fma2(acc[1][1], hp, wA.y);
                fma2(acc[1][2], hp, wB.x); fma2(acc[1][3], hp, wB.y);
                fma2(acc[1][4], hp, wC.x); fma2(acc[1][5], hp, wC.y);
                hp = pack2(h4.z, h4.z);
                fma2(acc[2][0], hp, wA.x); fma2(acc[2][1], hp, wA.y);
                fma2(acc[2][2], hp, wB.x); fma2(acc[2][3], hp, wB.y);
                fma2(acc[2][4], hp, wC.x); fma2(acc[2][5], hp, wC.y);
                hp = pack2(h4.w, h4.w);
                fma2(acc[3][0], hp, wA.x); fma2(acc[3][1], hp, wA.y);
                fma2(acc[3][2], hp, wB.x); fma2(acc[3][3], hp, wB.y);
                fma2(acc[3][4], hp, wC.x); fma2(acc[3][5], hp, wC.y);
            }

            // grab old-h values for the epilogue while their chunk is resident
            if (c == cj) {
#pragma unroll
                for (int ri = 0; ri < 4; ++ri)
                    hv[ri] = hb[((jbase & 127) + cg) * 128 + lane + 32 * ri];
            }
            __syncthreads();
        }

        // cross-warp reduction via smem
        {
            float vals[48];
#pragma unroll
            for (int r = 0; r < 4; ++r)
#pragma unroll
                for (int p = 0; p < 6; ++p) {
                    float2 f = unpack2(acc[r][p]);
                    vals[r * 12 + 2 * p]     = f.x;
                    vals[r * 12 + 2 * p + 1] = f.y;
                }
            float* dst = sRed + tid * 52;
#pragma unroll
            for (int q = 0; q < 12; ++q)
                *(float4*)(dst + q * 4) = *(const float4*)&vals[q * 4];
        }
        __syncthreads();

        // epilogue: thread handles (b = lane + 32*ri, column j = jbase + cg)
#pragma unroll
        for (int ri = 0; ri < 4; ++ri) {
            const int b = lane + 32 * ri;
            const int base = (b >> 2) * 52 + (b & 3) * 12 + cg * 3;
            float aR = 0.f, aZ = 0.f, aN = 0.f;
#pragma unroll
            for (int w = 0; w < 4; ++w) {
                const float* p = sRed + w * (32 * 52) + base;
                aR += p[0]; aZ += p[1]; aN += p[2];
            }
            const float gir = sGI[(0 * 128 + b) * 4 + cg];
            const float giz = sGI[(1 * 128 + b) * 4 + cg];
            const float gin = sGI[(2 * 128 + b) * 4 + cg];
            const float rr = 1.f / (1.f + expf(-(aR + gir)));
            const float zz = 1.f / (1.f + expf(-(aZ + giz)));
            const float nn = tanhf(gin + rr * (aN + bhn_j));
            const float nh = (1.f - zz) * nn + zz * hv[ri];
            out[((size_t)t * BB + b) * HH + j] = nh;
            // fold NEXT step's reset into the stored state (transposed, coalesced)
            hdst[(size_t)j * BB + b] = nh * g_RS[(t + 1) * BB + b];
        }

        grid_sync(NCTA, gen);
    }
}

// ---------------- launch ----------------
extern "C" void kernel_launch(void* const* d_in, const int* in_sizes, int n_in,
                              void* d_out, int out_size) {
    const float* x    = (const float*)d_in[0];   // [T,B,H]
    const void*  rst  = d_in[1];                 // [T,B] bool (unknown storage)
    const float* Wi   = (const float*)d_in[2];   // [H,3H]
    const float* bi   = (const float*)d_in[3];   // [3H]
    const float* Wh   = (const float*)d_in[4];   // [H,3H]
    const float* bhn  = (const float*)d_in[5];   // [H]
    const float* h0   = (const float*)d_in[6];   // [B,H]
    float* out = (float*)d_out;

    (void)in_sizes; (void)n_in; (void)out_size;

    // classify resets storage layout, then expand to fp32 keep-multipliers
    detect_reset_mode_kernel<<<1, 256>>>((const unsigned char*)rst);
    expand_resets_kernel<<<((TT + 1) * BB + 255) / 256, 256>>>(rst);

    // reset barrier state + load transposed h0 with keep(0) applied
    init_kernel<<<(BB * HH + 255) / 256, 256>>>(h0);

    // GI = x @ Wi + bi over all timesteps at once
    dim3 ggrid(H3 / GN, (TT * BB) / GM);   // (12, 512)
    gi_gemm_kernel<<<ggrid, 256>>>(x, Wi, bi);

    // persistent sequential scan
    cudaFuncSetAttribute(scan_kernel,
                         cudaFuncAttributeMaxDynamicSharedMemorySize, SCAN_SMEM_BYTES);
    scan_kernel<<<NCTA, SCAN_THREADS, SCAN_SMEM_BYTES>>>(Wh, bhn, out);
}

// round 7
// speedup vs baseline: 1.5536x; 1.5536x over previous
#include <cuda_runtime.h>
#include <math.h>

// Problem sizes (fixed by the reference)
#define TT 512
#define BB 128
#define HH 512
#define H3 1536

// ---------------- scratch (static __device__, no allocs) ----------------
__device__ float g_GI[TT * BB * H3];       // precomputed x@Wi + bi
__device__ float g_Ht[2 * HH * BB];        // TRANSPOSED hidden state [buf][j][b], reset pre-applied
__device__ float g_RS[(TT + 1) * BB];      // keep multipliers: 0 = reset, 1 = keep (row TT = 1)
__device__ int   g_reset_mode;             // 0=int32, 1=byte, 2=float32
__device__ unsigned int g_count;           // grid barrier arrive counter
__device__ unsigned int g_gen;             // grid barrier generation

// ---------------- f32x2 packed-FMA helpers (FFMA2) ----------------
__device__ __forceinline__ unsigned long long pack2(float lo, float hi) {
    unsigned long long r;
    asm("mov.b64 %0, {%1, %2};" : "=l"(r) : "f"(lo), "f"(hi));
    return r;
}
__device__ __forceinline__ float2 unpack2(unsigned long long v) {
    float2 f;
    asm("mov.b64 {%0, %1}, %2;" : "=f"(f.x), "=f"(f.y) : "l"(v));
    return f;
}
__device__ __forceinline__ void fma2(unsigned long long& d,
                                     unsigned long long a, unsigned long long b) {
    asm("fma.rn.f32x2 %0, %1, %2, %0;" : "+l"(d) : "l"(a), "l"(b));
}
// 16B async copy gmem -> smem (L1 bypass)
__device__ __forceinline__ void cp16(void* dst, const void* src) {
    unsigned s = (unsigned)__cvta_generic_to_shared(dst);
    asm volatile("cp.async.cg.shared.global [%0], [%1], 16;" :: "r"(s), "l"(src));
}

// ---------------- detect how the harness stored the bool resets ----------
__global__ void detect_reset_mode_kernel(const unsigned char* __restrict__ r) {
    __shared__ int cnt[4];
    if (threadIdx.x < 4) cnt[threadIdx.x] = 0;
    __syncthreads();
    int local[4] = {0, 0, 0, 0};
    const uchar4* r4 = (const uchar4*)r;
    for (int i = threadIdx.x; i < (TT * BB) / 4; i += blockDim.x) {
        uchar4 v = r4[i];
        local[0] += (v.x != 0); local[1] += (v.y != 0);
        local[2] += (v.z != 0); local[3] += (v.w != 0);
    }
#pragma unroll
    for (int q = 0; q < 4; ++q) atomicAdd(&cnt[q], local[q]);
    __syncthreads();
    if (threadIdx.x == 0) {
        int mode;
        if (cnt[1] > 0) mode = 1;                       // dense byte bools
        else if (cnt[0] > 0) mode = 0;                  // little-endian int32 0/1
        else if (cnt[2] > 0 || cnt[3] > 0) mode = 2;    // float32 0.0/1.0
        else mode = 0;
        g_reset_mode = mode;
    }
}

// ---------------- expand resets into fp32 keep-multipliers ----------------
__global__ void expand_resets_kernel(const void* __restrict__ resets) {
    int i = blockIdx.x * blockDim.x + threadIdx.x;
    if (i >= (TT + 1) * BB) return;
    if (i >= TT * BB) { g_RS[i] = 1.0f; return; }
    const int mode = g_reset_mode;
    bool rst;
    if (mode == 0)      rst = ((const int*)resets)[i] != 0;
    else if (mode == 1) rst = ((const unsigned char*)resets)[i] != 0;
    else                rst = ((const float*)resets)[i] != 0.0f;
    g_RS[i] = rst ? 0.0f : 1.0f;
}

// ---------------- init: reset barrier, load transposed h0 with keep(0) ----
__global__ void init_kernel(const float* __restrict__ h0) {
    int i = blockIdx.x * blockDim.x + threadIdx.x;
    if (i == 0) { g_count = 0u; g_gen = 0u; }
    if (i < BB * HH) {
        int b = i >> 9;          // / HH
        int j = i & (HH - 1);
        g_Ht[j * BB + b] = h0[i] * g_RS[b];
    }
}

// ---------------- GI GEMM: [65536,512] @ [512,1536] + bias (FFMA2) --------
#define GM 128
#define GN 128
#define GK 16

__global__ __launch_bounds__(256) void gi_gemm_kernel(
    const float* __restrict__ A,     // x as [T*B, H]
    const float* __restrict__ Bm,    // Wi [H, 3H]
    const float* __restrict__ bias)  // bi [3H]
{
    __shared__ float As[GK][GM];        // transposed A tile
    __shared__ float Bs[GK][GN + 4];    // padded B tile

    const int n0 = blockIdx.x * GN;
    const int m0 = blockIdx.y * GM;
    const int tid = threadIdx.x;
    const int tx = tid & 15;   // n direction
    const int ty = tid >> 4;   // m direction

    // acc pairs along n: acc2[i][jp] holds columns (2jp, 2jp+1)
    unsigned long long acc2[8][4];
#pragma unroll
    for (int i = 0; i < 8; ++i)
#pragma unroll
        for (int jp = 0; jp < 4; ++jp) acc2[i][jp] = 0ull;

    for (int k0 = 0; k0 < HH; k0 += GK) {
        // load A tile (128 rows x 16 k) as float4, store transposed
#pragma unroll
        for (int i = 0; i < 2; ++i) {
            int id = tid * 2 + i;            // 0..511
            int row = id >> 2;
            int c4 = id & 3;
            float4 v = *(const float4*)(A + (size_t)(m0 + row) * HH + k0 + c4 * 4);
            As[c4 * 4 + 0][row] = v.x;
            As[c4 * 4 + 1][row] = v.y;
            As[c4 * 4 + 2][row] = v.z;
            As[c4 * 4 + 3][row] = v.w;
        }
        // load B tile (16 k x 128 n)
#pragma unroll
        for (int i = 0; i < 2; ++i) {
            int id = tid * 2 + i;            // 0..511
            int kr = id >> 5;                // 0..15
            int n4 = id & 31;
            float4 v = *(const float4*)(Bm + (size_t)(k0 + kr) * H3 + n0 + n4 * 4);
            *(float4*)&Bs[kr][n4 * 4] = v;
        }
        __syncthreads();

#pragma unroll 8
        for (int kk = 0; kk < GK; ++kk) {
            float a[8];
            *(float4*)&a[0] = *(const float4*)&As[kk][ty * 8];
            *(float4*)&a[4] = *(const float4*)&As[kk][ty * 8 + 4];
            const ulonglong2 b01 = *(const ulonglong2*)&Bs[kk][tx * 8];
            const ulonglong2 b23 = *(const ulonglong2*)&Bs[kk][tx * 8 + 4];
#pragma unroll
            for (int i = 0; i < 8; ++i) {
                unsigned long long ai = pack2(a[i], a[i]);
                fma2(acc2[i][0], ai, b01.x);
                fma2(acc2[i][1], ai, b01.y);
                fma2(acc2[i][2], ai, b23.x);
                fma2(acc2[i][3], ai, b23.y);
            }
        }
        __syncthreads();
    }

    // epilogue: add bias, store
    float bb[8];
#pragma unroll
    for (int q = 0; q < 8; ++q) bb[q] = bias[n0 + tx * 8 + q];

#pragma unroll
    for (int i = 0; i < 8; ++i) {
        int m = m0 + ty * 8 + i;
        float* dst = g_GI + (size_t)m * H3 + n0 + tx * 8;
        float2 p0 = unpack2(acc2[i][0]);
        float2 p1 = unpack2(acc2[i][1]);
        float2 p2 = unpack2(acc2[i][2]);
        float2 p3 = unpack2(acc2[i][3]);
        float4 o0, o1;
        o0.x = p0.x + bb[0]; o0.y = p0.y + bb[1];
        o0.z = p1.x + bb[2]; o0.w = p1.y + bb[3];
        o1.x = p2.x + bb[4]; o1.y = p2.y + bb[5];
        o1.z = p3.x + bb[6]; o1.w = p3.y + bb[7];
        *(float4*)(dst + 0) = o0;
        *(float4*)(dst + 4) = o1;
    }
}

// ---------------- persistent scan kernel ----------------
#define NCTA 128
#define SCAN_THREADS 128

// smem layout (floats):
//   sWh  [512][12]          6144   (24KB) : this CTA's 12 gate-cols, [k][c], c = hcol*3+g
//   sHT  [2][128][128]     32768  (128KB) : double-buffered h^T chunks [k_local][b]
//   sGI  [3][128][4]        1536    (6KB) : staged gi slice for this step
//   sRed [4][32][52]        6656   (26KB) : per-warp partial sums (pad 52 vs 48)
#define SWH_OFF  0
#define SHT_OFF  6144
#define SGI_OFF  (6144 + 32768)
#define SRED_OFF (6144 + 32768 + 1536)
#define SCAN_SMEM_FLOATS (6144 + 32768 + 1536 + 6656)
#define SCAN_SMEM_BYTES (SCAN_SMEM_FLOATS * 4)

__device__ __forceinline__ void grid_sync(unsigned int nctas, unsigned int& gen) {
    __syncthreads();
    if (threadIdx.x == 0) {
        __threadfence();
        unsigned int prev = atomicAdd(&g_count, 1u);
        if (prev == nctas - 1u) {
            atomicExch(&g_count, 0u);
            __threadfence();
            atomicAdd(&g_gen, 1u);
        } else {
            unsigned int cur;
            do {
                asm volatile("ld.acquire.gpu.u32 %0, [%1];"
                             : "=r"(cur) : "l"(&g_gen) : "memory");
            } while (cur == gen);
        }
    }
    gen++;
    __syncthreads();
}

extern __shared__ float smf[];

__global__ __launch_bounds__(SCAN_THREADS, 1) void scan_kernel(
    const float* __restrict__ Wh,              // [H, 3H]
    const float* __restrict__ bhn,             // [H]
    float* __restrict__ out)                   // [T,B,H]
{
    float* sWh  = smf + SWH_OFF;
    float* sHT  = smf + SHT_OFF;
    float* sGI  = smf + SGI_OFF;
    float* sRed = smf + SRED_OFF;

    const int tid  = threadIdx.x;
    const int lane = tid & 31;
    const int wid  = tid >> 5;             // warp = k-slice owner AND epilogue col group
    const int jbase = blockIdx.x * 4;
    const int cj = jbase >> 7;             // chunk containing this CTA's h-columns
    const int cg = wid;
    const int j = jbase + cg;
    const float bhn_j = bhn[j];

    // load this CTA's 12 Wh gate-columns once: sWh[k*12 + c], c = hcol*3 + g
    for (int p = tid; p < 6144; p += SCAN_THREADS) {
        int k = p / 12, c = p % 12;
        sWh[p] = Wh[(size_t)k * H3 + (c % 3) * HH + jbase + c / 3];
    }
    __syncthreads();

    unsigned int gen = 0;

    for (int t = 0; t < TT; ++t) {
        const float* hsrc = g_Ht + (t & 1) * HH * BB;          // h^T, reset applied
        float* hdst       = g_Ht + ((t + 1) & 1) * HH * BB;
        const float* gi   = g_GI + (size_t)t * BB * H3;

        // stage chunk 0 (h^T rows 0..127) + gi slice  -> commit group
#pragma unroll
        for (int q = 0; q < 32; ++q) {
            int p = tid + q * SCAN_THREADS;
            int kr = p >> 5, c4 = p & 31;
            cp16(sHT + kr * 128 + c4 * 4, hsrc + (size_t)kr * BB + c4 * 4);
        }
#pragma unroll
        for (int g = 0; g < 3; ++g)
            cp16(sGI + (g * 128 + tid) * 4, gi + (size_t)tid * H3 + g * HH + jbase);
        asm volatile("cp.async.commit_group;");

        // per-warp k-slice accumulators: rows b = 4*lane + r, col-pairs (2p,2p+1)
        unsigned long long acc[4][6];
#pragma unroll
        for (int r = 0; r < 4; ++r)
#pragma unroll
            for (int p = 0; p < 6; ++p) acc[r][p] = 0ull;

        float hv[4];

        for (int c = 0; c < 4; ++c) {
            if (c < 3) {
                float* dstb = sHT + ((c + 1) & 1) * 16384;
#pragma unroll
                for (int q = 0; q < 32; ++q) {
                    int p = tid + q * SCAN_THREADS;
                    int kr = p >> 5, c4 = p & 31;
                    cp16(dstb + kr * 128 + c4 * 4,
                         hsrc + (size_t)((c + 1) * 128 + kr) * BB + c4 * 4);
                }
                asm volatile("cp.async.commit_group;");
                asm volatile("cp.async.wait_group 1;");
            } else {
                asm volatile("cp.async.wait_group 0;");
            }
            __syncthreads();

            const float* hb = sHT + (c & 1) * 16384;
            const float* hw = hb + (wid * 32) * 128;                 // warp's k rows
            const float* ww = sWh + (c * 128 + wid * 32) * 12;       // matching weights

#pragma unroll 4
            for (int kk = 0; kk < 32; ++kk) {
                const float4 h4 = *(const float4*)(hw + kk * 128 + lane * 4);
                const ulonglong2 wA = *(const ulonglong2*)(ww + kk * 12);
                const ulonglong2 wB = *(const ulonglong2*)(ww + kk * 12 + 4);
                const ulonglong2 wC = *(const ulonglong2*)(ww + kk * 12 + 8);
                unsigned long long hp;
                hp = pack2(h4.x, h4.x);
                fma2(acc[0][0], hp, wA.x); fma2(acc[0][1], hp, wA.y);
                fma2(acc[0][2], hp, wB.x); fma2(acc[0][3], hp, wB.y);
                fma2(acc[0][4], hp, wC.x); fma2(acc[0][5], hp, wC.y);
                hp = pack2(h4.y, h4.y);
                fma2(acc[1][0], hp, wA.x); fma2(acc[1][1], hp, wA.y);
                fma2(acc[1][2], hp, wB.x); fma2(acc[1][3], hp, wB.y);
                fma2(acc[1][4], hp, wC.x); fma2(acc[1][5], hp, wC.y);
                hp = pack2(h4.z, h4.z);
                fma2(acc[2][0], hp, wA.x); fma2(acc[2][1], hp, wA.y);
                fma2(acc[2][2], hp, wB.x); fma2(acc[2][3], hp, wB.y);
                fma2(acc[2][4], hp, wC.x); fma2(acc[2][5], hp, wC.y);
                hp = pack2(h4.w, h4.w);
                fma2(acc[3][0], hp, wA.x); fma2(acc[3][1], hp, wA.y);
                fma2(acc[3][2], hp, wB.x); fma2(acc[3][3], hp, wB.y);
                fma2(acc[3][4], hp, wC.x); fma2(acc[3][5], hp, wC.y);
            }

            // grab old-h values for the epilogue while their chunk is resident
            if (c == cj) {
#pragma unroll
                for (int ri = 0; ri < 4; ++ri)
                    hv[ri] = hb[((jbase & 127) + cg) * 128 + lane + 32 * ri];
            }
            __syncthreads();
        }

        // cross-warp reduction via smem
        {
            float vals[48];
#pragma unroll
            for (int r = 0; r < 4; ++r)
#pragma unroll
                for (int p = 0; p < 6; ++p) {
                    float2 f = unpack2(acc[r][p]);
                    vals[r * 12 + 2 * p]     = f.x;
                    vals[r * 12 + 2 * p + 1] = f.y;
                }
            float* dst = sRed + tid * 52;
#pragma unroll
            for (int q = 0; q < 12; ++q)
                *(float4*)(dst + q * 4) = *(const float4*)&vals[q * 4];
        }
        __syncthreads();

        // epilogue: thread handles (b = lane + 32*ri, column j = jbase + cg)
#pragma unroll
        for (int ri = 0; ri < 4; ++ri) {
            const int b = lane + 32 * ri;
            const int base = (b >> 2) * 52 + (b & 3) * 12 + cg * 3;
            float aR = 0.f, aZ = 0.f, aN = 0.f;
#pragma unroll
            for (int w = 0; w < 4; ++w) {
                const float* p = sRed + w * (32 * 52) + base;
                aR += p[0]; aZ += p[1]; aN += p[2];
            }
            const float gir = sGI[(0 * 128 + b) * 4 + cg];
            const float giz = sGI[(1 * 128 + b) * 4 + cg];
            const float gin = sGI[(2 * 128 + b) * 4 + cg];
            const float rr = 1.f / (1.f + expf(-(aR + gir)));
            const float zz = 1.f / (1.f + expf(-(aZ + giz)));
            const float nn = tanhf(gin + rr * (aN + bhn_j));
            const float nh = (1.f - zz) * nn + zz * hv[ri];
            out[((size_t)t * BB + b) * HH + j] = nh;
            // fold NEXT step's reset into the stored state (transposed, coalesced)
            hdst[(size_t)j * BB + b] = nh * g_RS[(t + 1) * BB + b];
        }

        grid_sync(NCTA, gen);
    }
}

// ---------------- launch ----------------
extern "C" void kernel_launch(void* const* d_in, const int* in_sizes, int n_in,
                              void* d_out, int out_size) {
    const float* x    = (const float*)d_in[0];   // [T,B,H]
    const void*  rst  = d_in[1];                 // [T,B] bool (unknown storage)
    const float* Wi   = (const float*)d_in[2];   // [H,3H]
    const float* bi   = (const float*)d_in[3];   // [3H]
    const float* Wh   = (const float*)d_in[4];   // [H,3H]
    const float* bhn  = (const float*)d_in[5];   // [H]
    const float* h0   = (const float*)d_in[6];   // [B,H]
    float* out = (float*)d_out;

    (void)in_sizes; (void)n_in; (void)out_size;

    // classify resets storage layout, then expand to fp32 keep-multipliers
    detect_reset_mode_kernel<<<1, 256>>>((const unsigned char*)rst);
    expand_resets_kernel<<<((TT + 1) * BB + 255) / 256, 256>>>(rst);

    // reset barrier state + load transposed h0 with keep(0) applied
    init_kernel<<<(BB * HH + 255) / 256, 256>>>(h0);

    // GI = x @ Wi + bi over all timesteps at once
    dim3 ggrid(H3 / GN, (TT * BB) / GM);   // (12, 512)
    gi_gemm_kernel<<<ggrid, 256>>>(x, Wi, bi);

    // persistent sequential scan
    cudaFuncSetAttribute(scan_kernel,
                         cudaFuncAttributeMaxDynamicSharedMemorySize, SCAN_SMEM_BYTES);
    scan_kernel<<<NCTA, SCAN_THREADS, SCAN_SMEM_BYTES>>>(Wh, bhn, out);
}

// round 8
// speedup vs baseline: 1.7979x; 1.1573x over previous
#include <cuda_runtime.h>
#include <math.h>

// Problem sizes (fixed by the reference)
#define TT 512
#define BB 128
#define HH 512
#define H3 1536

// ---------------- scratch (static __device__, no allocs) ----------------
__device__ float g_GI[TT * BB * H3];       // precomputed x@Wi + bi
__device__ float g_Ht[2 * HH * BB];        // TRANSPOSED hidden state [buf][j][b], reset pre-applied
__device__ float g_RS[(TT + 1) * BB];      // keep multipliers: 0 = reset, 1 = keep (row TT = 1)
__device__ int   g_reset_mode;             // 0=int32, 1=byte, 2=float32
__device__ unsigned int g_count;           // grid barrier arrive counter
__device__ unsigned int g_gen;             // grid barrier generation

// ---------------- f32x2 packed-FMA helpers (FFMA2) ----------------
__device__ __forceinline__ unsigned long long pack2(float lo, float hi) {
    unsigned long long r;
    asm("mov.b64 %0, {%1, %2};" : "=l"(r) : "f"(lo), "f"(hi));
    return r;
}
__device__ __forceinline__ float2 unpack2(unsigned long long v) {
    float2 f;
    asm("mov.b64 {%0, %1}, %2;" : "=f"(f.x), "=f"(f.y) : "l"(v));
    return f;
}
__device__ __forceinline__ void fma2(unsigned long long& d,
                                     unsigned long long a, unsigned long long b) {
    asm("fma.rn.f32x2 %0, %1, %2, %0;" : "+l"(d) : "l"(a), "l"(b));
}
// 16B async copy gmem -> smem (L1 bypass)
__device__ __forceinline__ void cp16(void* dst, const void* src) {
    unsigned s = (unsigned)__cvta_generic_to_shared(dst);
    asm volatile("cp.async.cg.shared.global [%0], [%1], 16;" :: "r"(s), "l"(src));
}

// ---------------- detect how the harness stored the bool resets ----------
__global__ void detect_reset_mode_kernel(const unsigned char* __restrict__ r) {
    __shared__ int cnt[4];
    if (threadIdx.x < 4) cnt[threadIdx.x] = 0;
    __syncthreads();
    int local[4] = {0, 0, 0, 0};
    const uchar4* r4 = (const uchar4*)r;
    for (int i = threadIdx.x; i < (TT * BB) / 4; i += blockDim.x) {
        uchar4 v = r4[i];
        local[0] += (v.x != 0); local[1] += (v.y != 0);
        local[2] += (v.z != 0); local[3] += (v.w != 0);
    }
#pragma unroll
    for (int q = 0; q < 4; ++q) atomicAdd(&cnt[q], local[q]);
    __syncthreads();
    if (threadIdx.x == 0) {
        int mode;
        if (cnt[1] > 0) mode = 1;                       // dense byte bools
        else if (cnt[0] > 0) mode = 0;                  // little-endian int32 0/1
        else if (cnt[2] > 0 || cnt[3] > 0) mode = 2;    // float32 0.0/1.0
        else mode = 0;
        g_reset_mode = mode;
    }
}

// ---------------- expand resets into fp32 keep-multipliers ----------------
__global__ void expand_resets_kernel(const void* __restrict__ resets) {
    int i = blockIdx.x * blockDim.x + threadIdx.x;
    if (i >= (TT + 1) * BB) return;
    if (i >= TT * BB) { g_RS[i] = 1.0f; return; }
    const int mode = g_reset_mode;
    bool rst;
    if (mode == 0)      rst = ((const int*)resets)[i] != 0;
    else if (mode == 1) rst = ((const unsigned char*)resets)[i] != 0;
    else                rst = ((const float*)resets)[i] != 0.0f;
    g_RS[i] = rst ? 0.0f : 1.0f;
}

// ---------------- init: reset barrier, load transposed h0 with keep(0) ----
__global__ void init_kernel(const float* __restrict__ h0) {
    int i = blockIdx.x * blockDim.x + threadIdx.x;
    if (i == 0) { g_count = 0u; g_gen = 0u; }
    if (i < BB * HH) {
        int b = i >> 9;          // / HH
        int j = i & (HH - 1);
        g_Ht[j * BB + b] = h0[i] * g_RS[b];
    }
}

// ---------------- GI GEMM: [65536,512] @ [512,1536] + bias (FFMA2, pipelined)
#define GM 128
#define GN 128
#define GK 16

__global__ __launch_bounds__(256) void gi_gemm_kernel(
    const float* __restrict__ A,     // x as [T*B, H]
    const float* __restrict__ Bm,    // Wi [H, 3H]
    const float* __restrict__ bias)  // bi [3H]
{
    __shared__ float As[2][GK][GM];        // transposed A tiles (double buffered)
    __shared__ float Bs[2][GK][GN + 4];    // padded B tiles (double buffered)

    const int n0 = blockIdx.x * GN;
    const int m0 = blockIdx.y * GM;
    const int tid = threadIdx.x;
    const int tx = tid & 15;   // n direction
    const int ty = tid >> 4;   // m direction

    // per-thread A-tile load ids (two float4 per tile)
    const int id0 = tid * 2, id1 = tid * 2 + 1;
    const int ar0 = id0 >> 2, ac0 = id0 & 3;
    const int ar1 = id1 >> 2, ac1 = id1 & 3;
    // per-thread B-tile cp.async ids
    const int bk0 = id0 >> 5, bn0 = id0 & 31;
    const int bk1 = id1 >> 5, bn1 = id1 & 31;

    unsigned long long acc2[8][4];
#pragma unroll
    for (int i = 0; i < 8; ++i)
#pragma unroll
        for (int jp = 0; jp < 4; ++jp) acc2[i][jp] = 0ull;

    // prologue: tile 0
    {
        float4 v0 = *(const float4*)(A + (size_t)(m0 + ar0) * HH + 0 + ac0 * 4);
        float4 v1 = *(const float4*)(A + (size_t)(m0 + ar1) * HH + 0 + ac1 * 4);
        As[0][ac0 * 4 + 0][ar0] = v0.x; As[0][ac0 * 4 + 1][ar0] = v0.y;
        As[0][ac0 * 4 + 2][ar0] = v0.z; As[0][ac0 * 4 + 3][ar0] = v0.w;
        As[0][ac1 * 4 + 0][ar1] = v1.x; As[0][ac1 * 4 + 1][ar1] = v1.y;
        As[0][ac1 * 4 + 2][ar1] = v1.z; As[0][ac1 * 4 + 3][ar1] = v1.w;
        cp16(&Bs[0][bk0][bn0 * 4], Bm + (size_t)bk0 * H3 + n0 + bn0 * 4);
        cp16(&Bs[0][bk1][bn1 * 4], Bm + (size_t)bk1 * H3 + n0 + bn1 * 4);
        asm volatile("cp.async.commit_group;");
        asm volatile("cp.async.wait_group 0;");
    }
    __syncthreads();

    for (int it = 0; it < HH / GK; ++it) {
        const int cur = it & 1, nxt = cur ^ 1;
        const bool has_next = (it < HH / GK - 1);
        float4 nA0, nA1;
        if (has_next) {
            const int k0 = (it + 1) * GK;
            nA0 = *(const float4*)(A + (size_t)(m0 + ar0) * HH + k0 + ac0 * 4);
            nA1 = *(const float4*)(A + (size_t)(m0 + ar1) * HH + k0 + ac1 * 4);
            cp16(&Bs[nxt][bk0][bn0 * 4], Bm + (size_t)(k0 + bk0) * H3 + n0 + bn0 * 4);
            cp16(&Bs[nxt][bk1][bn1 * 4], Bm + (size_t)(k0 + bk1) * H3 + n0 + bn1 * 4);
            asm volatile("cp.async.commit_group;");
        }

#pragma unroll 8
        for (int kk = 0; kk < GK; ++kk) {
            float a[8];
            *(float4*)&a[0] = *(const float4*)&As[cur][kk][ty * 8];
            *(float4*)&a[4] = *(const float4*)&As[cur][kk][ty * 8 + 4];
            const ulonglong2 b01 = *(const ulonglong2*)&Bs[cur][kk][tx * 8];
            const ulonglong2 b23 = *(const ulonglong2*)&Bs[cur][kk][tx * 8 + 4];
#pragma unroll
            for (int i = 0; i < 8; ++i) {
                unsigned long long ai = pack2(a[i], a[i]);
                fma2(acc2[i][0], ai, b01.x);
                fma2(acc2[i][1], ai, b01.y);
                fma2(acc2[i][2], ai, b23.x);
                fma2(acc2[i][3], ai, b23.y);
            }
        }

        if (has_next) {
            As[nxt][ac0 * 4 + 0][ar0] = nA0.x; As[nxt][ac0 * 4 + 1][ar0] = nA0.y;
            As[nxt][ac0 * 4 + 2][ar0] = nA0.z; As[nxt][ac0 * 4 + 3][ar0] = nA0.w;
            As[nxt][ac1 * 4 + 0][ar1] = nA1.x; As[nxt][ac1 * 4 + 1][ar1] = nA1.y;
            As[nxt][ac1 * 4 + 2][ar1] = nA1.z; As[nxt][ac1 * 4 + 3][ar1] = nA1.w;
            asm volatile("cp.async.wait_group 0;");
        }
        __syncthreads();
    }

    // epilogue: add bias, store
    float bb[8];
#pragma unroll
    for (int q = 0; q < 8; ++q) bb[q] = bias[n0 + tx * 8 + q];

#pragma unroll
    for (int i = 0; i < 8; ++i) {
        int m = m0 + ty * 8 + i;
        float* dst = g_GI + (size_t)m * H3 + n0 + tx * 8;
        float2 p0 = unpack2(acc2[i][0]);
        float2 p1 = unpack2(acc2[i][1]);
        float2 p2 = unpack2(acc2[i][2]);
        float2 p3 = unpack2(acc2[i][3]);
        float4 o0, o1;
        o0.x = p0.x + bb[0]; o0.y = p0.y + bb[1];
        o0.z = p1.x + bb[2]; o0.w = p1.y + bb[3];
        o1.x = p2.x + bb[4]; o1.y = p2.y + bb[5];
        o1.z = p3.x + bb[6]; o1.w = p3.y + bb[7];
        *(float4*)(dst + 0) = o0;
        *(float4*)(dst + 4) = o1;
    }
}

// ---------------- persistent scan kernel (2D partition: 4 b-groups x 32 j-groups)
#define NCTA 128
#define SCAN_THREADS 128

// smem layout (floats):
//   sWh  [512][48]        24576   (96KB) : CTA's 48 gate-cols, [k][c], c = jl*3+g
//   sHT  [2][128][32]      8192   (32KB) : double-buffered h^T chunks [k_local][b_local]
//   sGI  [3][32][16]       1536    (6KB) : staged gi slice for this step
//   sRed [4][32][52]       6656   (26KB) : per-warp partial sums (pad 52 vs 48)
#define SWH_OFF  0
#define SHT_OFF  24576
#define SGI_OFF  (24576 + 8192)
#define SRED_OFF (24576 + 8192 + 1536)
#define SCAN_SMEM_FLOATS (24576 + 8192 + 1536 + 6656)
#define SCAN_SMEM_BYTES (SCAN_SMEM_FLOATS * 4)

__device__ __forceinline__ void grid_sync(unsigned int nctas, unsigned int& gen) {
    __syncthreads();
    if (threadIdx.x == 0) {
        __threadfence();
        unsigned int prev = atomicAdd(&g_count, 1u);
        if (prev == nctas - 1u) {
            atomicExch(&g_count, 0u);
            __threadfence();
            atomicAdd(&g_gen, 1u);
        } else {
            unsigned int cur;
            do {
                asm volatile("ld.acquire.gpu.u32 %0, [%1];"
                             : "=r"(cur) : "l"(&g_gen) : "memory");
            } while (cur == gen);
        }
    }
    gen++;
    __syncthreads();
}

extern __shared__ float smf[];

__global__ __launch_bounds__(SCAN_THREADS, 1) void scan_kernel(
    const float* __restrict__ Wh,              // [H, 3H]
    const float* __restrict__ bhn,             // [H]
    float* __restrict__ out)                   // [T,B,H]
{
    float* sWh  = smf + SWH_OFF;
    float* sHT  = smf + SHT_OFF;
    float* sGI  = smf + SGI_OFF;
    float* sRed = smf + SRED_OFF;

    const int tid  = threadIdx.x;
    const int lane = tid & 31;
    const int wid  = tid >> 5;              // k-slice owner within chunk
    const int ji   = blockIdx.x & 31;       // 32 column groups of 16
    const int bi   = blockIdx.x >> 5;       // 4 batch groups of 32
    const int jbase = ji * 16;
    const int bbase = bi * 32;
    const int cj = jbase >> 7;              // chunk containing this CTA's h-columns
    // microkernel lane mapping
    const int gq = lane >> 3;               // 0..3 -> 12 gate-cols each
    const int bq = lane & 7;                // 0..7 -> 4 b's each
    // epilogue mapping
    const int eb = tid & 31;                // local b
    const int jq = tid >> 5;                // group of 4 j's

    // load this CTA's 48 Wh gate-columns once: sWh[k*48 + c], c = jl*3 + g
    for (int p = tid; p < 512 * 48; p += SCAN_THREADS) {
        int k = p / 48, c = p % 48;
        sWh[p] = Wh[(size_t)k * H3 + (c % 3) * HH + jbase + c / 3];
    }
    float bhn_j[4];
#pragma unroll
    for (int ii = 0; ii < 4; ++ii) bhn_j[ii] = bhn[jbase + jq * 4 + ii];
    __syncthreads();

    unsigned int gen = 0;

    for (int t = 0; t < TT; ++t) {
        const float* hsrc = g_Ht + (t & 1) * HH * BB;          // h^T, reset applied
        float* hdst       = g_Ht + ((t + 1) & 1) * HH * BB;
        const float* gi   = g_GI + (size_t)t * BB * H3;

        // stage chunk 0 (k rows 0..127, 32 b) + gi slice -> one commit group
#pragma unroll
        for (int q = 0; q < 8; ++q) {
            int p = tid + q * SCAN_THREADS;      // 0..1023
            int kr = p >> 3, seg = p & 7;
            cp16(sHT + kr * 32 + seg * 4, hsrc + (size_t)kr * BB + bbase + seg * 4);
        }
#pragma unroll
        for (int q = 0; q < 3; ++q) {
            int p = tid + q * SCAN_THREADS;      // 0..383
            int g = p >> 7, rem = p & 127;
            int b = rem >> 2, j4 = rem & 3;
            cp16(sGI + (g * 32 + b) * 16 + j4 * 4,
                 gi + (size_t)(bbase + b) * H3 + g * HH + jbase + j4 * 4);
        }
        asm volatile("cp.async.commit_group;");

        // accumulators: rows b_local = bq*4 + r, gate-col pairs (gq*12 + 2p, +1)
        unsigned long long acc[4][6];
#pragma unroll
        for (int r = 0; r < 4; ++r)
#pragma unroll
            for (int p = 0; p < 6; ++p) acc[r][p] = 0ull;

        float hv[4];

        for (int c = 0; c < 4; ++c) {
            if (c < 3) {
                float* dstb = sHT + ((c + 1) & 1) * 4096;
#pragma unroll
                for (int q = 0; q < 8; ++q) {
                    int p = tid + q * SCAN_THREADS;
                    int kr = p >> 3, seg = p & 7;
                    cp16(dstb + kr * 32 + seg * 4,
                         hsrc + (size_t)((c + 1) * 128 + kr) * BB + bbase + seg * 4);
                }
                asm volatile("cp.async.commit_group;");
                asm volatile("cp.async.wait_group 1;");
            } else {
                asm volatile("cp.async.wait_group 0;");
            }
            __syncthreads();

            const float* hb = sHT + (c & 1) * 4096;
            const float* hw = hb + (wid * 32) * 32;                 // warp's 32 k rows
            const float* ww = sWh + (c * 128 + wid * 32) * 48 + gq * 12;

#pragma unroll 4
            for (int kk = 0; kk < 32; ++kk) {
                const float4 h4 = *(const float4*)(hw + kk * 32 + bq * 4);
                const ulonglong2 wA = *(const ulonglong2*)(ww + kk * 48);
                const ulonglong2 wB = *(const ulonglong2*)(ww + kk * 48 + 4);
                const ulonglong2 wC = *(const ulonglong2*)(ww + kk * 48 + 8);
                unsigned long long hp;
                hp = pack2(h4.x, h4.x);
                fma2(acc[0][0], hp, wA.x); fma2(acc[0][1], hp, wA.y);
                fma2(acc[0][2], hp, wB.x); fma2(acc[0][3], hp, wB.y);
                fma2(acc[0][4], hp, wC.x); fma2(acc[0][5], hp, wC.y);
                hp = pack2(h4.y, h4.y);
                fma2(acc[1][0], hp, wA.x); fma2(acc[1][1], hp, wA.y);
                fma2(acc[1][2], hp, wB.x); fma2(acc[1][3], hp, wB.y);
                fma2(acc[1][4], hp, wC.x); fma2(acc[1][5], hp, wC.y);
                hp = pack2(h4.z, h4.z);
                fma2(acc[2][0], hp, wA.x); fma2(acc[2][1], hp, wA.y);
                fma2(acc[2][2], hp, wB.x); fma2(acc[2][3], hp, wB.y);
                fma2(acc[2][4], hp, wC.x); fma2(acc[2][5], hp, wC.y);
                hp = pack2(h4.w, h4.w);
                fma2(acc[3][0], hp, wA.x); fma2(acc[3][1], hp, wA.y);
                fma2(acc[3][2], hp, wB.x); fma2(acc[3][3], hp, wB.y);
                fma2(acc[3][4], hp, wC.x); fma2(acc[3][5], hp, wC.y);
            }

            // grab old-h values for the epilogue while their chunk is resident
            if (c == cj) {
                const int kb = (jbase & 127) + jq * 4;
#pragma unroll
                for (int ii = 0; ii < 4; ++ii)
                    hv[ii] = hb[(kb + ii) * 32 + eb];
            }
            __syncthreads();
        }

        // cross-warp reduction via smem
        {
            float vals[48];
#pragma unroll
            for (int r = 0; r < 4; ++r)
#pragma unroll
                for (int p = 0; p < 6; ++p) {
                    float2 f = unpack2(acc[r][p]);
                    vals[r * 12 + 2 * p]     = f.x;
                    vals[r * 12 + 2 * p + 1] = f.y;
                }
            float* dst = sRed + tid * 52;
#pragma unroll
            for (int q = 0; q < 12; ++q)
                *(float4*)(dst + q * 4) = *(const float4*)&vals[q * 4];
        }
        __syncthreads();

        // epilogue: thread handles (b = eb, j = jbase + jq*4 + ii), ii = 0..3
        const float rs = g_RS[(t + 1) * BB + bbase + eb];
        const int lane_owner = jq * 8 + (eb >> 2);
        const int rbase = lane_owner * 52 + (eb & 3) * 12;
        float4 nh4;
        float nhv[4];
#pragma unroll
        for (int ii = 0; ii < 4; ++ii) {
            float aR = 0.f, aZ = 0.f, aN = 0.f;
#pragma unroll
            for (int w = 0; w < 4; ++w) {
                const float* p = sRed + w * (32 * 52) + rbase + ii * 3;
                aR += p[0]; aZ += p[1]; aN += p[2];
            }
            const int jl = jq * 4 + ii;
            const float gir = sGI[(0 * 32 + eb) * 16 + jl];
            const float giz = sGI[(1 * 32 + eb) * 16 + jl];
            const float gin = sGI[(2 * 32 + eb) * 16 + jl];
            const float rr = 1.f / (1.f + expf(-(aR + gir)));
            const float zz = 1.f / (1.f + expf(-(aZ + giz)));
            const float nn = tanhf(gin + rr * (aN + bhn_j[ii]));
            nhv[ii] = (1.f - zz) * nn + zz * hv[ii];
        }
        nh4.x = nhv[0]; nh4.y = nhv[1]; nh4.z = nhv[2]; nh4.w = nhv[3];
        // coalesced-ish float4 output write (4 consecutive j)
        *(float4*)(out + ((size_t)t * BB + bbase + eb) * HH + jbase + jq * 4) = nh4;
        // recurrent state (transposed, coalesced across eb), next reset folded in
#pragma unroll
        for (int ii = 0; ii < 4; ++ii)
            hdst[(size_t)(jbase + jq * 4 + ii) * BB + bbase + eb] = nhv[ii] * rs;

        grid_sync(NCTA, gen);
    }
}

// ---------------- launch ----------------
extern "C" void kernel_launch(void* const* d_in, const int* in_sizes, int n_in,
                              void* d_out, int out_size) {
    const float* x    = (const float*)d_in[0];   // [T,B,H]
    const void*  rst  = d_in[1];                 // [T,B] bool (unknown storage)
    const float* Wi   = (const float*)d_in[2];   // [H,3H]
    const float* bi   = (const float*)d_in[3];   // [3H]
    const float* Wh   = (const float*)d_in[4];   // [H,3H]
    const float* bhn  = (const float*)d_in[5];   // [H]
    const float* h0   = (const float*)d_in[6];   // [B,H]
    float* out = (float*)d_out;

    (void)in_sizes; (void)n_in; (void)out_size;

    // classify resets storage layout, then expand to fp32 keep-multipliers
    detect_reset_mode_kernel<<<1, 256>>>((const unsigned char*)rst);
    expand_resets_kernel<<<((TT + 1) * BB + 255) / 256, 256>>>(rst);

    // reset barrier state + load transposed h0 with keep(0) applied
    init_kernel<<<(BB * HH + 255) / 256, 256>>>(h0);

    // GI = x @ Wi + bi over all timesteps at once
    dim3 ggrid(H3 / GN, (TT * BB) / GM);   // (12, 512)
    gi_gemm_kernel<<<ggrid, 256>>>(x, Wi, bi);

    // persistent sequential scan
    cudaFuncSetAttribute(scan_kernel,
                         cudaFuncAttributeMaxDynamicSharedMemorySize, SCAN_SMEM_BYTES);
    scan_kernel<<<NCTA, SCAN_THREADS, SCAN_SMEM_BYTES>>>(Wh, bhn, out);
}

// round 10
// speedup vs baseline: 2.0884x; 1.1616x over previous
#include <cuda_runtime.h>
#include <cuda_bf16.h>
#include <math.h>
#include <cstdint>

// Problem sizes (fixed by the reference)
#define TT 512
#define BB 128
#define HH 512
#define H3 1536
#define KP 1536   // split-K' = 3*HH

// ---------------- scratch (static __device__, no allocs) ----------------
__device__ float g_GI[TT * BB * H3];                  // x@Wi + bi (fp32)
__device__ __nv_bfloat16 g_A2[(size_t)TT * BB * KP];  // A' = [x_hi | x_lo | x_hi]
__device__ __nv_bfloat16 g_WT[(size_t)H3 * KP];       // W'^T[n][k'] = [Whi;Whi;Wlo]
__device__ float g_Ht[2 * HH * BB];                   // transposed hidden state
__device__ float g_RS[(TT + 1) * BB];                 // keep multipliers (0 = reset)
__device__ int   g_reset_mode;
__device__ unsigned int g_cnt[4];                     // per-group barrier counters
__device__ unsigned int g_gen2[4];                    // per-group barrier generations

// ---------------- small PTX helpers ----------------
__device__ __forceinline__ unsigned long long pack2(float lo, float hi) {
    unsigned long long r;
    asm("mov.b64 %0, {%1, %2};" : "=l"(r) : "f"(lo), "f"(hi));
    return r;
}
__device__ __forceinline__ float2 unpack2(unsigned long long v) {
    float2 f;
    asm("mov.b64 {%0, %1}, %2;" : "=f"(f.x), "=f"(f.y) : "l"(v));
    return f;
}
__device__ __forceinline__ void fma2(unsigned long long& d,
                                     unsigned long long a, unsigned long long b) {
    asm("fma.rn.f32x2 %0, %1, %2, %0;" : "+l"(d) : "l"(a), "l"(b));
}
__device__ __forceinline__ void cp16(void* dst, const void* src) {
    unsigned s = (unsigned)__cvta_generic_to_shared(dst);
    asm volatile("cp.async.cg.shared.global [%0], [%1], 16;" :: "r"(s), "l"(src));
}
__device__ __forceinline__ uint32_t smem_u32(const void* p) {
    return (uint32_t)__cvta_generic_to_shared(p);
}
__device__ __forceinline__ void ldsm_x4(uint32_t& r0, uint32_t& r1,
                                        uint32_t& r2, uint32_t& r3, uint32_t addr) {
    asm volatile("ldmatrix.sync.aligned.m8n8.x4.shared.b16 {%0,%1,%2,%3}, [%4];"
                 : "=r"(r0), "=r"(r1), "=r"(r2), "=r"(r3) : "r"(addr));
}
__device__ __forceinline__ void mma_bf16(float* d, const uint32_t* a,
                                         uint32_t b0, uint32_t b1) {
    asm volatile("mma.sync.aligned.m16n8k16.row.col.f32.bf16.bf16.f32 "
                 "{%0,%1,%2,%3}, {%4,%5,%6,%7}, {%8,%9}, {%0,%1,%2,%3};"
                 : "+f"(d[0]), "+f"(d[1]), "+f"(d[2]), "+f"(d[3])
                 : "r"(a[0]), "r"(a[1]), "r"(a[2]), "r"(a[3]), "r"(b0), "r"(b1));
}

// ---------------- detect how the harness stored the bool resets ----------
__global__ void detect_reset_mode_kernel(const unsigned char* __restrict__ r) {
    __shared__ int cnt[4];
    if (threadIdx.x < 4) cnt[threadIdx.x] = 0;
    __syncthreads();
    int local[4] = {0, 0, 0, 0};
    const uchar4* r4 = (const uchar4*)r;
    for (int i = threadIdx.x; i < (TT * BB) / 4; i += blockDim.x) {
        uchar4 v = r4[i];
        local[0] += (v.x != 0); local[1] += (v.y != 0);
        local[2] += (v.z != 0); local[3] += (v.w != 0);
    }
#pragma unroll
    for (int q = 0; q < 4; ++q) atomicAdd(&cnt[q], local[q]);
    __syncthreads();
    if (threadIdx.x == 0) {
        int mode;
        if (cnt[1] > 0) mode = 1;
        else if (cnt[0] > 0) mode = 0;
        else if (cnt[2] > 0 || cnt[3] > 0) mode = 2;
        else mode = 0;
        g_reset_mode = mode;
    }
}

__global__ void expand_resets_kernel(const void* __restrict__ resets) {
    int i = blockIdx.x * blockDim.x + threadIdx.x;
    if (i >= (TT + 1) * BB) return;
    if (i >= TT * BB) { g_RS[i] = 1.0f; return; }
    const int mode = g_reset_mode;
    bool rst;
    if (mode == 0)      rst = ((const int*)resets)[i] != 0;
    else if (mode == 1) rst = ((const unsigned char*)resets)[i] != 0;
    else                rst = ((const float*)resets)[i] != 0.0f;
    g_RS[i] = rst ? 0.0f : 1.0f;
}

__global__ void init_kernel(const float* __restrict__ h0) {
    int i = blockIdx.x * blockDim.x + threadIdx.x;
    if (i < 4) { g_cnt[i] = 0u; g_gen2[i] = 0u; }
    if (i < BB * HH) {
        int b = i >> 9;
        int j = i & (HH - 1);
        g_Ht[j * BB + b] = h0[i] * g_RS[b];
    }
}

// ---------------- split-fp32 -> bf16 conversion kernels ----------------
__global__ void convert_x_kernel(const float* __restrict__ x) {
    const int n = TT * BB * HH;
    for (int idx = blockIdx.x * blockDim.x + threadIdx.x; idx < n;
         idx += gridDim.x * blockDim.x) {
        int m = idx >> 9, k = idx & 511;
        float v = x[idx];
        __nv_bfloat16 hi = __float2bfloat16(v);
        __nv_bfloat16 lo = __float2bfloat16(v - __bfloat162float(hi));
        size_t base = (size_t)m * KP;
        g_A2[base + k] = hi;
        g_A2[base + 512 + k] = lo;
        g_A2[base + 1024 + k] = hi;
    }
}
__global__ void convert_w_kernel(const float* __restrict__ Wi) {
    const int n = HH * H3;
    for (int idx = blockIdx.x * blockDim.x + threadIdx.x; idx < n;
         idx += gridDim.x * blockDim.x) {
        int k = idx / H3, c = idx % H3;          // Wi[k][c]
        float v = Wi[idx];
        __nv_bfloat16 hi = __float2bfloat16(v);
        __nv_bfloat16 lo = __float2bfloat16(v - __bfloat162float(hi));
        size_t base = (size_t)c * KP;
        g_WT[base + k] = hi;
        g_WT[base + 512 + k] = hi;
        g_WT[base + 1024 + k] = lo;
    }
}

// ---------------- GI GEMM via mma.sync bf16 (HMMA) -----------------------
// C[65536,1536] = A2[65536,1536] @ WT[1536,1536]^T, fp32 accum, + bias.
// CTA tile 128x128, BK=32, 3-stage cp.async pipeline, padded smem rows (80B).
#define HBM_M 128
#define HBM_N 128
#define HBM_K 32
#define APITCH 40                    // elems per smem row (80 B)
#define STAGE_BYTES 20480            // A 10240 + B 10240
#define NSTAGE 3
#define HB_BIAS_OFF (NSTAGE * STAGE_BYTES)
#define HB_SMEM_BYTES (HB_BIAS_OFF + 512)
#define NC (KP / HBM_K)              // 48 chunks

extern __shared__ float smf[];

__device__ __forceinline__ void hmma_stage(char* smc, int slot, int kc,
                                           const __nv_bfloat16* Ag,
                                           const __nv_bfloat16* Bg, int tid) {
    char* sA = smc + slot * STAGE_BYTES;
    char* sB = sA + 10240;
    const int k0 = kc * HBM_K;
#pragma unroll
    for (int i = 0; i < 2; ++i) {
        int id = tid * 2 + i;              // 0..511
        int row = id >> 2, seg = id & 3;   // 128 rows x 4 16B segs
        cp16(sA + row * 80 + seg * 16, Ag + (size_t)row * KP + k0 + seg * 8);
        cp16(sB + row * 80 + seg * 16, Bg + (size_t)row * KP + k0 + seg * 8);
    }
}

__global__ __launch_bounds__(256) void gi_hmma_kernel(const float* __restrict__ bias) {
    char* smc = (char*)smf;
    const uint32_t sbase = smem_u32(smc);
    const int tid = threadIdx.x;
    const int lane = tid & 31, warp = tid >> 5;
    const int wm = warp >> 1, wn = warp & 1;      // 4x2 warp grid

    // L2-friendly block swizzle: 8 m-tiles per n sweep
    const int bid = blockIdx.x;                   // 0..6143
    const int grp = bid / 96, r = bid % 96;
    const int ntile = r % 12, mtile = grp * 8 + r / 12;
    const int m0 = mtile * HBM_M, n0 = ntile * HBM_N;
    const __nv_bfloat16* Ag = g_A2 + (size_t)m0 * KP;
    const __nv_bfloat16* Bg = g_WT + (size_t)n0 * KP;

    // bias slice
    float* bsm = (float*)(smc + HB_BIAS_OFF);
    if (tid < 128) bsm[tid] = bias[n0 + tid];

    float acc[2][8][4];
#pragma unroll
    for (int mt = 0; mt < 2; ++mt)
#pragma unroll
        for (int nt = 0; nt < 8; ++nt)
#pragma unroll
            for (int q = 0; q < 4; ++q) acc[mt][nt][q] = 0.f;

    // prologue
    hmma_stage(smc, 0, 0, Ag, Bg, tid);
    asm volatile("cp.async.commit_group;");
    hmma_stage(smc, 1, 1, Ag, Bg, tid);
    asm volatile("cp.async.commit_group;");

    const int lrow = lane & 15;
    const int lcol8 = (lane >> 4) * 8;

    for (int c = 0; c < NC; ++c) {
        if (c == NC - 1) asm volatile("cp.async.wait_group 0;");
        else             asm volatile("cp.async.wait_group 1;");
        __syncthreads();
        if (c + 2 < NC) {
            hmma_stage(smc, (c + 2) % NSTAGE, c + 2, Ag, Bg, tid);
            asm volatile("cp.async.commit_group;");
        }

        const uint32_t aBase = sbase + (uint32_t)(c % NSTAGE) * STAGE_BYTES;
        const uint32_t bBase = aBase + 10240;

#pragma unroll
        for (int ks = 0; ks < 2; ++ks) {
            const int col = ks * 16 + lcol8;
            uint32_t af[2][4];
#pragma unroll
            for (int mt = 0; mt < 2; ++mt) {
                uint32_t addr = aBase +
                    (uint32_t)((wm * 32 + mt * 16 + lrow) * APITCH + col) * 2;
                ldsm_x4(af[mt][0], af[mt][1], af[mt][2], af[mt][3], addr);
            }
            uint32_t bf[4][4];
#pragma unroll
            for (int ng = 0; ng < 4; ++ng) {
                uint32_t addr = bBase +
                    (uint32_t)((wn * 64 + ng * 16 + lrow) * APITCH + col) * 2;
                ldsm_x4(bf[ng][0], bf[ng][1], bf[ng][2], bf[ng][3], addr);
            }
#pragma unroll
            for (int mt = 0; mt < 2; ++mt)
#pragma unroll
                for (int ng = 0; ng < 4; ++ng) {
                    mma_bf16(acc[mt][ng * 2 + 0], af[mt], bf[ng][0], bf[ng][2]);
                    mma_bf16(acc[mt][ng * 2 + 1], af[mt], bf[ng][1], bf[ng][3]);
                }
        }
        __syncthreads();
    }

    // epilogue: add bias, store fp32 (frag: rows l/4, l/4+8; cols 2*(l%4), +1)
    const int ml = lane >> 2;
    const int nl = (lane & 3) * 2;
#pragma unroll
    for (int mt = 0; mt < 2; ++mt) {
        const int mg = m0 + wm * 32 + mt * 16 + ml;
#pragma unroll
        for (int nt = 0; nt < 8; ++nt) {
            const int ncol = wn * 64 + nt * 8 + nl;
            const float b0 = bsm[ncol], b1 = bsm[ncol + 1];
            float2 v0, v1;
            v0.x = acc[mt][nt][0] + b0; v0.y = acc[mt][nt][1] + b1;
            v1.x = acc[mt][nt][2] + b0; v1.y = acc[mt][nt][3] + b1;
            *(float2*)(g_GI + (size_t)mg * H3 + n0 + ncol) = v0;
            *(float2*)(g_GI + (size_t)(mg + 8) * H3 + n0 + ncol) = v1;
        }
    }
}

// ---------------- persistent scan kernel (4 independent 32-CTA groups) ----
#define NCTA 128
#define SCAN_THREADS 128

#define SWH_OFF  0
#define SHT_OFF  24576
#define SGI_OFF  (24576 + 8192)
#define SRED_OFF (24576 + 8192 + 1536)
#define SCAN_SMEM_FLOATS (24576 + 8192 + 1536 + 6656)
#define SCAN_SMEM_BYTES (SCAN_SMEM_FLOATS * 4)

__device__ __forceinline__ void group_sync(int bi, unsigned int& gen) {
    __syncthreads();
    if (threadIdx.x == 0) {
        unsigned int prev;
        asm volatile("atom.acq_rel.gpu.add.u32 %0, [%1], 1;"
                     : "=r"(prev) : "l"(&g_cnt[bi]) : "memory");
        if (prev == 31u) {
            asm volatile("st.relaxed.gpu.u32 [%0], 0;" :: "l"(&g_cnt[bi]) : "memory");
            unsigned int d;
            asm volatile("atom.release.gpu.add.u32 %0, [%1], 1;"
                         : "=r"(d) : "l"(&g_gen2[bi]) : "memory");
        } else {
            unsigned int cur;
            do {
                asm volatile("ld.acquire.gpu.u32 %0, [%1];"
                             : "=r"(cur) : "l"(&g_gen2[bi]) : "memory");
            } while (cur == gen);
        }
    }
    gen++;
    __syncthreads();
}

__global__ __launch_bounds__(SCAN_THREADS, 1) void scan_kernel(
    const float* __restrict__ Wh,              // [H, 3H]
    const float* __restrict__ bhn,             // [H]
    float* __restrict__ out)                   // [T,B,H]
{
    float* sWh  = smf + SWH_OFF;
    float* sHT  = smf + SHT_OFF;
    float* sGI  = smf + SGI_OFF;
    float* sRed = smf + SRED_OFF;

    const int tid  = threadIdx.x;
    const int lane = tid & 31;
    const int wid  = tid >> 5;
    const int ji   = blockIdx.x & 31;
    const int bi   = blockIdx.x >> 5;
    const int jbase = ji * 16;
    const int bbase = bi * 32;
    const int cj = jbase >> 7;
    const int gq = lane >> 3;
    const int bq = lane & 7;
    const int eb = tid & 31;
    const int jq = tid >> 5;

    for (int p = tid; p < 512 * 48; p += SCAN_THREADS) {
        int k = p / 48, c = p % 48;
        sWh[p] = Wh[(size_t)k * H3 + (c % 3) * HH + jbase + c / 3];
    }
    float bhn_j[4];
#pragma unroll
    for (int ii = 0; ii < 4; ++ii) bhn_j[ii] = bhn[jbase + jq * 4 + ii];
    __syncthreads();

    unsigned int gen = 0;

    for (int t = 0; t < TT; ++t) {
        const float* hsrc = g_Ht + (t & 1) * HH * BB;
        float* hdst       = g_Ht + ((t + 1) & 1) * HH * BB;
        const float* gi   = g_GI + (size_t)t * BB * H3;

#pragma unroll
        for (int q = 0; q < 8; ++q) {
            int p = tid + q * SCAN_THREADS;
            int kr = p >> 3, seg = p & 7;
            cp16(sHT + kr * 32 + seg * 4, hsrc + (size_t)kr * BB + bbase + seg * 4);
        }
#pragma unroll
        for (int q = 0; q < 3; ++q) {
            int p = tid + q * SCAN_THREADS;
            int g = p >> 7, rem = p & 127;
            int b = rem >> 2, j4 = rem & 3;
            cp16(sGI + (g * 32 + b) * 16 + j4 * 4,
                 gi + (size_t)(bbase + b) * H3 + g * HH + jbase + j4 * 4);
        }
        asm volatile("cp.async.commit_group;");

        unsigned long long acc[4][6];
#pragma unroll
        for (int r = 0; r < 4; ++r)
#pragma unroll
            for (int p = 0; p < 6; ++p) acc[r][p] = 0ull;

        float hv[4];

        for (int c = 0; c < 4; ++c) {
            if (c < 3) {
                float* dstb = sHT + ((c + 1) & 1) * 4096;
#pragma unroll
                for (int q = 0; q < 8; ++q) {
                    int p = tid + q * SCAN_THREADS;
                    int kr = p >> 3, seg = p & 7;
                    cp16(dstb + kr * 32 + seg * 4,
                         hsrc + (size_t)((c + 1) * 128 + kr) * BB + bbase + seg * 4);
                }
                asm volatile("cp.async.commit_group;");
                asm volatile("cp.async.wait_group 1;");
            } else {
                asm volatile("cp.async.wait_group 0;");
            }
            __syncthreads();

            const float* hb = sHT + (c & 1) * 4096;
            const float* hw = hb + (wid * 32) * 32;
            const float* ww = sWh + (c * 128 + wid * 32) * 48 + gq * 12;

#pragma unroll 4
            for (int kk = 0; kk < 32; ++kk) {
                const float4 h4 = *(const float4*)(hw + kk * 32 + bq * 4);
                const ulonglong2 wA = *(const ulonglong2*)(ww + kk * 48);
                const ulonglong2 wB = *(const ulonglong2*)(ww + kk * 48 + 4);
                const ulonglong2 wC = *(const ulonglong2*)(ww + kk * 48 + 8);
                unsigned long long hp;
                hp = pack2(h4.x, h4.x);
                fma2(acc[0][0], hp, wA.x); fma2(acc[0][1], hp, wA.y);
                fma2(acc[0][2], hp, wB.x); fma2(acc[0][3], hp, wB.y);
                fma2(acc[0][4], hp, wC.x); fma2(acc[0][5], hp, wC.y);
                hp = pack2(h4.y, h4.y);
                fma2(acc[1][0], hp, wA.x); fma2(acc[1][1], hp, wA.y);
                fma2(acc[1][2], hp, wB.x); fma2(acc[1][3], hp, wB.y);
                fma2(acc[1][4], hp, wC.x); fma2(acc[1][5], hp, wC.y);
                hp = pack2(h4.z, h4.z);
                fma2(acc[2][0], hp, wA.x); fma2(acc[2][1], hp, wA.y);
                fma2(acc[2][2], hp, wB.x); fma2(acc[2][3], hp, wB.y);
                fma2(acc[2][4], hp, wC.x); fma2(acc[2][5], hp, wC.y);
                hp = pack2(h4.w, h4.w);
                fma2(acc[3][0], hp, wA.x); fma2(acc[3][1], hp, wA.y);
                fma2(acc[3][2], hp, wB.x); fma2(acc[3][3], hp, wB.y);
                fma2(acc[3][4], hp, wC.x); fma2(acc[3][5], hp, wC.y);
            }

            if (c == cj) {
                const int kb = (jbase & 127) + jq * 4;
#pragma unroll
                for (int ii = 0; ii < 4; ++ii)
                    hv[ii] = hb[(kb + ii) * 32 + eb];
            }
            __syncthreads();
        }

        {
            float vals[48];
#pragma unroll
            for (int r = 0; r < 4; ++r)
#pragma unroll
                for (int p = 0; p < 6; ++p) {
                    float2 f = unpack2(acc[r][p]);
                    vals[r * 12 + 2 * p]     = f.x;
                    vals[r * 12 + 2 * p + 1] = f.y;
                }
            float* dst = sRed + tid * 52;
#pragma unroll
            for (int q = 0; q < 12; ++q)
                *(float4*)(dst + q * 4) = *(const float4*)&vals[q * 4];
        }
        __syncthreads();

        const float rs = g_RS[(t + 1) * BB + bbase + eb];
        const int lane_owner = jq * 8 + (eb >> 2);
        const int rbase = lane_owner * 52 + (eb & 3) * 12;
        float nhv[4];
#pragma unroll
        for (int ii = 0; ii < 4; ++ii) {
            float aR = 0.f, aZ = 0.f, aN = 0.f;
#pragma unroll
            for (int w = 0; w < 4; ++w) {
                const float* p = sRed + w * (32 * 52) + rbase + ii * 3;
                aR += p[0]; aZ += p[1]; aN += p[2];
            }
            const int jl = jq * 4 + ii;
            const float gir = sGI[(0 * 32 + eb) * 16 + jl];
            const float giz = sGI[(1 * 32 + eb) * 16 + jl];
            const float gin = sGI[(2 * 32 + eb) * 16 + jl];
            const float rr = 1.f / (1.f + expf(-(aR + gir)));
            const float zz = 1.f / (1.f + expf(-(aZ + giz)));
            const float nn = tanhf(gin + rr * (aN + bhn_j[ii]));
            nhv[ii] = (1.f - zz) * nn + zz * hv[ii];
        }
        float4 nh4;
        nh4.x = nhv[0]; nh4.y = nhv[1]; nh4.z = nhv[2]; nh4.w = nhv[3];
        *(float4*)(out + ((size_t)t * BB + bbase + eb) * HH + jbase + jq * 4) = nh4;
#pragma unroll
        for (int ii = 0; ii < 4; ++ii)
            hdst[(size_t)(jbase + jq * 4 + ii) * BB + bbase + eb] = nhv[ii] * rs;

        group_sync(bi, gen);
    }
}

// ---------------- launch ----------------
extern "C" void kernel_launch(void* const* d_in, const int* in_sizes, int n_in,
                              void* d_out, int out_size) {
    const float* x    = (const float*)d_in[0];   // [T,B,H]
    const void*  rst  = d_in[1];                 // [T,B] bool (unknown storage)
    const float* Wi   = (const float*)d_in[2];   // [H,3H]
    const float* bi   = (const float*)d_in[3];   // [3H]
    const float* Wh   = (const float*)d_in[4];   // [H,3H]
    const float* bhn  = (const float*)d_in[5];   // [H]
    const float* h0   = (const float*)d_in[6];   // [B,H]
    float* out = (float*)d_out;

    (void)in_sizes; (void)n_in; (void)out_size;

    detect_reset_mode_kernel<<<1, 256>>>((const unsigned char*)rst);
    expand_resets_kernel<<<((TT + 1) * BB + 255) / 256, 256>>>(rst);
    init_kernel<<<(BB * HH + 255) / 256, 256>>>(h0);

    // split-fp32 -> bf16 operand build
    convert_x_kernel<<<4096, 256>>>(x);
    convert_w_kernel<<<1024, 256>>>(Wi);

    // GI = x @ Wi + bi via HMMA bf16 (split-K' = 1536)
    cudaFuncSetAttribute(gi_hmma_kernel,
                         cudaFuncAttributeMaxDynamicSharedMemorySize, HB_SMEM_BYTES);
    gi_hmma_kernel<<<6144, 256, HB_SMEM_BYTES>>>(bi);

    // persistent sequential scan
    cudaFuncSetAttribute(scan_kernel,
                         cudaFuncAttributeMaxDynamicSharedMemorySize, SCAN_SMEM_BYTES);
    scan_kernel<<<NCTA, SCAN_THREADS, SCAN_SMEM_BYTES>>>(Wh, bhn, out);
}

// round 11
// speedup vs baseline: 2.1483x; 1.0287x over previous
#include <cuda_runtime.h>
#include <cuda_bf16.h>
#include <math.h>
#include <cstdint>

// Problem sizes (fixed by the reference)
#define TT 512
#define BB 128
#define HH 512
#define H3 1536
#define KP 1536   // split-K' = 3*HH

// ---------------- scratch (static __device__, no allocs) ----------------
__device__ float g_GI[TT * BB * H3];                  // x@Wi + bi (fp32)
__device__ __nv_bfloat16 g_A2[(size_t)TT * BB * KP];  // A' = [x_hi | x_lo | x_hi]
__device__ __nv_bfloat16 g_WT[(size_t)H3 * KP];       // W'^T[n][k'] = [Whi;Whi;Wlo]
__device__ float g_Ht[2 * HH * BB];                   // transposed hidden state
__device__ float g_RS[(TT + 1) * BB];                 // keep multipliers (0 = reset)
__device__ int   g_reset_mode;
__device__ unsigned int g_cnt[4];                     // per-group barrier counters
__device__ unsigned int g_gen2[4];                    // per-group barrier generations

// ---------------- small PTX helpers ----------------
__device__ __forceinline__ unsigned long long pack2(float lo, float hi) {
    unsigned long long r;
    asm("mov.b64 %0, {%1, %2};" : "=l"(r) : "f"(lo), "f"(hi));
    return r;
}
__device__ __forceinline__ float2 unpack2(unsigned long long v) {
    float2 f;
    asm("mov.b64 {%0, %1}, %2;" : "=f"(f.x), "=f"(f.y) : "l"(v));
    return f;
}
__device__ __forceinline__ void fma2(unsigned long long& d,
                                     unsigned long long a, unsigned long long b) {
    asm("fma.rn.f32x2 %0, %1, %2, %0;" : "+l"(d) : "l"(a), "l"(b));
}
__device__ __forceinline__ void cp16(void* dst, const void* src) {
    unsigned s = (unsigned)__cvta_generic_to_shared(dst);
    asm volatile("cp.async.cg.shared.global [%0], [%1], 16;" :: "r"(s), "l"(src));
}
__device__ __forceinline__ uint32_t smem_u32(const void* p) {
    return (uint32_t)__cvta_generic_to_shared(p);
}
__device__ __forceinline__ void ldsm_x4(uint32_t& r0, uint32_t& r1,
                                        uint32_t& r2, uint32_t& r3, uint32_t addr) {
    asm volatile("ldmatrix.sync.aligned.m8n8.x4.shared.b16 {%0,%1,%2,%3}, [%4];"
                 : "=r"(r0), "=r"(r1), "=r"(r2), "=r"(r3) : "r"(addr));
}
__device__ __forceinline__ void mma_bf16(float* d, const uint32_t* a,
                                         uint32_t b0, uint32_t b1) {
    asm volatile("mma.sync.aligned.m16n8k16.row.col.f32.bf16.bf16.f32 "
                 "{%0,%1,%2,%3}, {%4,%5,%6,%7}, {%8,%9}, {%0,%1,%2,%3};"
                 : "+f"(d[0]), "+f"(d[1]), "+f"(d[2]), "+f"(d[3])
                 : "r"(a[0]), "r"(a[1]), "r"(a[2]), "r"(a[3]), "r"(b0), "r"(b1));
}
// fast activations: ex2.approx/rcp.approx (rel err ~2^-22), clamped
__device__ __forceinline__ float fsigmoid(float x) {
    x = fminf(30.f, fmaxf(-30.f, x));
    float e;
    asm("ex2.approx.f32 %0, %1;" : "=f"(e) : "f"(-1.4426950408889634f * x));
    float r;
    asm("rcp.approx.f32 %0, %1;" : "=f"(r) : "f"(1.0f + e));
    return r;
}
__device__ __forceinline__ float ftanh_fast(float x) {
    x = fminf(30.f, fmaxf(-30.f, x));
    float e;
    asm("ex2.approx.f32 %0, %1;" : "=f"(e) : "f"(-2.8853900817779268f * x));
    float r;
    asm("rcp.approx.f32 %0, %1;" : "=f"(r) : "f"(1.0f + e));
    return (1.0f - e) * r;
}

// ---------------- detect how the harness stored the bool resets ----------
__global__ void detect_reset_mode_kernel(const unsigned char* __restrict__ r) {
    __shared__ int cnt[4];
    if (threadIdx.x < 4) cnt[threadIdx.x] = 0;
    __syncthreads();
    int local[4] = {0, 0, 0, 0};
    const uchar4* r4 = (const uchar4*)r;
    for (int i = threadIdx.x; i < (TT * BB) / 4; i += blockDim.x) {
        uchar4 v = r4[i];
        local[0] += (v.x != 0); local[1] += (v.y != 0);
        local[2] += (v.z != 0); local[3] += (v.w != 0);
    }
#pragma unroll
    for (int q = 0; q < 4; ++q) atomicAdd(&cnt[q], local[q]);
    __syncthreads();
    if (threadIdx.x == 0) {
        int mode;
        if (cnt[1] > 0) mode = 1;
        else if (cnt[0] > 0) mode = 0;
        else if (cnt[2] > 0 || cnt[3] > 0) mode = 2;
        else mode = 0;
        g_reset_mode = mode;
    }
}

__global__ void expand_resets_kernel(const void* __restrict__ resets) {
    int i = blockIdx.x * blockDim.x + threadIdx.x;
    if (i >= (TT + 1) * BB) return;
    if (i >= TT * BB) { g_RS[i] = 1.0f; return; }
    const int mode = g_reset_mode;
    bool rst;
    if (mode == 0)      rst = ((const int*)resets)[i] != 0;
    else if (mode == 1) rst = ((const unsigned char*)resets)[i] != 0;
    else                rst = ((const float*)resets)[i] != 0.0f;
    g_RS[i] = rst ? 0.0f : 1.0f;
}

__global__ void init_kernel(const float* __restrict__ h0) {
    int i = blockIdx.x * blockDim.x + threadIdx.x;
    if (i < 4) { g_cnt[i] = 0u; g_gen2[i] = 0u; }
    if (i < BB * HH) {
        int b = i >> 9;
        int j = i & (HH - 1);
        g_Ht[j * BB + b] = h0[i] * g_RS[b];
    }
}

// ---------------- split-fp32 -> bf16 conversion kernels ----------------
__global__ void convert_x_kernel(const float* __restrict__ x) {
    const int n = TT * BB * HH;
    for (int idx = blockIdx.x * blockDim.x + threadIdx.x; idx < n;
         idx += gridDim.x * blockDim.x) {
        int m = idx >> 9, k = idx & 511;
        float v = x[idx];
        __nv_bfloat16 hi = __float2bfloat16(v);
        __nv_bfloat16 lo = __float2bfloat16(v - __bfloat162float(hi));
        size_t base = (size_t)m * KP;
        g_A2[base + k] = hi;
        g_A2[base + 512 + k] = lo;
        g_A2[base + 1024 + k] = hi;
    }
}
__global__ void convert_w_kernel(const float* __restrict__ Wi) {
    const int n = HH * H3;
    for (int idx = blockIdx.x * blockDim.x + threadIdx.x; idx < n;
         idx += gridDim.x * blockDim.x) {
        int k = idx / H3, c = idx % H3;          // Wi[k][c]
        float v = Wi[idx];
        __nv_bfloat16 hi = __float2bfloat16(v);
        __nv_bfloat16 lo = __float2bfloat16(v - __bfloat162float(hi));
        size_t base = (size_t)c * KP;
        g_WT[base + k] = hi;
        g_WT[base + 512 + k] = hi;
        g_WT[base + 1024 + k] = lo;
    }
}

// ---------------- GI GEMM via mma.sync bf16 (HMMA) -----------------------
#define HBM_M 128
#define HBM_N 128
#define HBM_K 32
#define APITCH 40                    // elems per smem row (80 B)
#define STAGE_BYTES 20480            // A 10240 + B 10240
#define NSTAGE 3
#define HB_BIAS_OFF (NSTAGE * STAGE_BYTES)
#define HB_SMEM_BYTES (HB_BIAS_OFF + 512)
#define NC (KP / HBM_K)              // 48 chunks

extern __shared__ float smf[];

__device__ __forceinline__ void hmma_stage(char* smc, int slot, int kc,
                                           const __nv_bfloat16* Ag,
                                           const __nv_bfloat16* Bg, int tid) {
    char* sA = smc + slot * STAGE_BYTES;
    char* sB = sA + 10240;
    const int k0 = kc * HBM_K;
#pragma unroll
    for (int i = 0; i < 2; ++i) {
        int id = tid * 2 + i;              // 0..511
        int row = id >> 2, seg = id & 3;   // 128 rows x 4 16B segs
        cp16(sA + row * 80 + seg * 16, Ag + (size_t)row * KP + k0 + seg * 8);
        cp16(sB + row * 80 + seg * 16, Bg + (size_t)row * KP + k0 + seg * 8);
    }
}

__global__ __launch_bounds__(256) void gi_hmma_kernel(const float* __restrict__ bias) {
    char* smc = (char*)smf;
    const uint32_t sbase = smem_u32(smc);
    const int tid = threadIdx.x;
    const int lane = tid & 31, warp = tid >> 5;
    const int wm = warp >> 1, wn = warp & 1;      // 4x2 warp grid

    const int bid = blockIdx.x;                   // 0..6143
    const int grp = bid / 96, r = bid % 96;
    const int ntile = r % 12, mtile = grp * 8 + r / 12;
    const int m0 = mtile * HBM_M, n0 = ntile * HBM_N;
    const __nv_bfloat16* Ag = g_A2 + (size_t)m0 * KP;
    const __nv_bfloat16* Bg = g_WT + (size_t)n0 * KP;

    float* bsm = (float*)(smc + HB_BIAS_OFF);
    if (tid < 128) bsm[tid] = bias[n0 + tid];

    float acc[2][8][4];
#pragma unroll
    for (int mt = 0; mt < 2; ++mt)
#pragma unroll
        for (int nt = 0; nt < 8; ++nt)
#pragma unroll
            for (int q = 0; q < 4; ++q) acc[mt][nt][q] = 0.f;

    hmma_stage(smc, 0, 0, Ag, Bg, tid);
    asm volatile("cp.async.commit_group;");
    hmma_stage(smc, 1, 1, Ag, Bg, tid);
    asm volatile("cp.async.commit_group;");

    const int lrow = lane & 15;
    const int lcol8 = (lane >> 4) * 8;

    for (int c = 0; c < NC; ++c) {
        if (c == NC - 1) asm volatile("cp.async.wait_group 0;");
        else             asm volatile("cp.async.wait_group 1;");
        __syncthreads();
        if (c + 2 < NC) {
            hmma_stage(smc, (c + 2) % NSTAGE, c + 2, Ag, Bg, tid);
            asm volatile("cp.async.commit_group;");
        }

        const uint32_t aBase = sbase + (uint32_t)(c % NSTAGE) * STAGE_BYTES;
        const uint32_t bBase = aBase + 10240;

#pragma unroll
        for (int ks = 0; ks < 2; ++ks) {
            const int col = ks * 16 + lcol8;
            uint32_t af[2][4];
#pragma unroll
            for (int mt = 0; mt < 2; ++mt) {
                uint32_t addr = aBase +
                    (uint32_t)((wm * 32 + mt * 16 + lrow) * APITCH + col) * 2;
                ldsm_x4(af[mt][0], af[mt][1], af[mt][2], af[mt][3], addr);
            }
            uint32_t bf[4][4];
#pragma unroll
            for (int ng = 0; ng < 4; ++ng) {
                uint32_t addr = bBase +
                    (uint32_t)((wn * 64 + ng * 16 + lrow) * APITCH + col) * 2;
                ldsm_x4(bf[ng][0], bf[ng][1], bf[ng][2], bf[ng][3], addr);
            }
#pragma unroll
            for (int mt = 0; mt < 2; ++mt)
#pragma unroll
                for (int ng = 0; ng < 4; ++ng) {
                    mma_bf16(acc[mt][ng * 2 + 0], af[mt], bf[ng][0], bf[ng][2]);
                    mma_bf16(acc[mt][ng * 2 + 1], af[mt], bf[ng][1], bf[ng][3]);
                }
        }
        __syncthreads();
    }

    const int ml = lane >> 2;
    const int nl = (lane & 3) * 2;
#pragma unroll
    for (int mt = 0; mt < 2; ++mt) {
        const int mg = m0 + wm * 32 + mt * 16 + ml;
#pragma unroll
        for (int nt = 0; nt < 8; ++nt) {
            const int ncol = wn * 64 + nt * 8 + nl;
            const float b0 = bsm[ncol], b1 = bsm[ncol + 1];
            float2 v0, v1;
            v0.x = acc[mt][nt][0] + b0; v0.y = acc[mt][nt][1] + b1;
            v1.x = acc[mt][nt][2] + b0; v1.y = acc[mt][nt][3] + b1;
            *(float2*)(g_GI + (size_t)mg * H3 + n0 + ncol) = v0;
            *(float2*)(g_GI + (size_t)(mg + 8) * H3 + n0 + ncol) = v1;
        }
    }
}

// ---------------- persistent scan kernel (single-shot staging) -----------
#define NCTA 128
#define SCAN_THREADS 128

// smem layout (floats):
//   sWh  [512][48]      24576  (96KB)
//   sH   [512][32]      16384  (64KB)  full h slice, [k][b_local]
//   sGI  [2][3][32][16]  3072  (12KB)  double-buffered gi slice
//   sRed [4][32][52]     6656  (26KB)
#define SWH_OFF  0
#define SH_OFF   24576
#define SGI_OFF  (24576 + 16384)
#define SRED_OFF (24576 + 16384 + 3072)
#define SCAN_SMEM_FLOATS (24576 + 16384 + 3072 + 6656)
#define SCAN_SMEM_BYTES (SCAN_SMEM_FLOATS * 4)

__device__ __forceinline__ void group_sync(int bi, unsigned int& gen) {
    __syncthreads();
    if (threadIdx.x == 0) {
        unsigned int prev;
        asm volatile("atom.acq_rel.gpu.add.u32 %0, [%1], 1;"
                     : "=r"(prev) : "l"(&g_cnt[bi]) : "memory");
        if (prev == 31u) {
            asm volatile("st.relaxed.gpu.u32 [%0], 0;" :: "l"(&g_cnt[bi]) : "memory");
            unsigned int d;
            asm volatile("atom.release.gpu.add.u32 %0, [%1], 1;"
                         : "=r"(d) : "l"(&g_gen2[bi]) : "memory");
        } else {
            unsigned int cur;
            do {
                asm volatile("ld.acquire.gpu.u32 %0, [%1];"
                             : "=r"(cur) : "l"(&g_gen2[bi]) : "memory");
            } while (cur == gen);
        }
    }
    gen++;
    __syncthreads();
}

__global__ __launch_bounds__(SCAN_THREADS, 1) void scan_kernel(
    const float* __restrict__ Wh,              // [H, 3H]
    const float* __restrict__ bhn,             // [H]
    float* __restrict__ out)                   // [T,B,H]
{
    float* sWh  = smf + SWH_OFF;
    float* sH   = smf + SH_OFF;
    float* sGI  = smf + SGI_OFF;
    float* sRed = smf + SRED_OFF;

    const int tid  = threadIdx.x;
    const int lane = tid & 31;
    const int wid  = tid >> 5;
    const int ji   = blockIdx.x & 31;
    const int bi   = blockIdx.x >> 5;
    const int jbase = ji * 16;
    const int bbase = bi * 32;
    const int gq = lane >> 3;
    const int bq = lane & 7;
    const int eb = tid & 31;
    const int jq = tid >> 5;

    // weights resident: sWh[k*48 + c], c = jl*3 + g
    for (int p = tid; p < 512 * 48; p += SCAN_THREADS) {
        int k = p / 48, c = p % 48;
        sWh[p] = Wh[(size_t)k * H3 + (c % 3) * HH + jbase + c / 3];
    }
    float bhn_j[4];
#pragma unroll
    for (int ii = 0; ii < 4; ++ii) bhn_j[ii] = bhn[jbase + jq * 4 + ii];

    // prefetch gi for t=0 into buffer 0
#pragma unroll
    for (int q = 0; q < 3; ++q) {
        int p = tid + q * SCAN_THREADS;
        int g = p >> 7, rem = p & 127;
        int b = rem >> 2, j4 = rem & 3;
        cp16(sGI + (g * 32 + b) * 16 + j4 * 4,
             g_GI + (size_t)(bbase + b) * H3 + g * HH + jbase + j4 * 4);
    }
    asm volatile("cp.async.commit_group;");
    __syncthreads();

    unsigned int gen = 0;

    for (int t = 0; t < TT; ++t) {
        const float* hsrc = g_Ht + (t & 1) * HH * BB;
        float* hdst       = g_Ht + ((t + 1) & 1) * HH * BB;

        // stage FULL h slice [512 k][32 b] in one shot (32 cp16/thread)
#pragma unroll
        for (int q = 0; q < 32; ++q) {
            int p = tid + q * SCAN_THREADS;    // 0..4095 float4 units
            int k = p >> 3, seg = p & 7;
            cp16(sH + k * 32 + seg * 4, hsrc + (size_t)k * BB + bbase + seg * 4);
        }
        asm volatile("cp.async.commit_group;");
        asm volatile("cp.async.wait_group 0;");   // waits h + pending gi prefetch
        __syncthreads();

        // compute: warp wid owns k rows [wid*128, wid*128+128)
        unsigned long long acc[4][6];
#pragma unroll
        for (int r = 0; r < 4; ++r)
#pragma unroll
            for (int p = 0; p < 6; ++p) acc[r][p] = 0ull;

        const float* hw = sH + (wid * 128) * 32;
        const float* ww = sWh + (wid * 128) * 48 + gq * 12;

#pragma unroll 4
        for (int kk = 0; kk < 128; ++kk) {
            const float4 h4 = *(const float4*)(hw + kk * 32 + bq * 4);
            const ulonglong2 wA = *(const ulonglong2*)(ww + kk * 48);
            const ulonglong2 wB = *(const ulonglong2*)(ww + kk * 48 + 4);
            const ulonglong2 wC = *(const ulonglong2*)(ww + kk * 48 + 8);
            unsigned long long hp;
            hp = pack2(h4.x, h4.x);
            fma2(acc[0][0], hp, wA.x); fma2(acc[0][1], hp, wA.y);
            fma2(acc[0][2], hp, wB.x); fma2(acc[0][3], hp, wB.y);
            fma2(acc[0][4], hp, wC.x); fma2(acc[0][5], hp, wC.y);
            hp = pack2(h4.y, h4.y);
            fma2(acc[1][0], hp, wA.x); fma2(acc[1][1], hp, wA.y);
            fma2(acc[1][2], hp, wB.x); fma2(acc[1][3], hp, wB.y);
            fma2(acc[1][4], hp, wC.x); fma2(acc[1][5], hp, wC.y);
            hp = pack2(h4.z, h4.z);
            fma2(acc[2][0], hp, wA.x); fma2(acc[2][1], hp, wA.y);
            fma2(acc[2][2], hp, wB.x); fma2(acc[2][3], hp, wB.y);
            fma2(acc[2][4], hp, wC.x); fma2(acc[2][5], hp, wC.y);
            hp = pack2(h4.w, h4.w);
            fma2(acc[3][0], hp, wA.x); fma2(acc[3][1], hp, wA.y);
            fma2(acc[3][2], hp, wB.x); fma2(acc[3][3], hp, wB.y);
            fma2(acc[3][4], hp, wC.x); fma2(acc[3][5], hp, wC.y);
        }

        // old-h values for epilogue (full h resident in smem)
        float hv[4];
#pragma unroll
        for (int ii = 0; ii < 4; ++ii)
            hv[ii] = sH[(jbase + jq * 4 + ii) * 32 + eb];

        // cross-warp reduction via smem
        {
            float vals[48];
#pragma unroll
            for (int r = 0; r < 4; ++r)
#pragma unroll
                for (int p = 0; p < 6; ++p) {
                    float2 f = unpack2(acc[r][p]);
                    vals[r * 12 + 2 * p]     = f.x;
                    vals[r * 12 + 2 * p + 1] = f.y;
                }
            float* dst = sRed + tid * 52;
#pragma unroll
            for (int q = 0; q < 12; ++q)
                *(float4*)(dst + q * 4) = *(const float4*)&vals[q * 4];
        }
        __syncthreads();

        // epilogue: thread handles (b = eb, j = jbase + jq*4 + ii)
        const float* gib = sGI + (t & 1) * 1536;
        const float rs = g_RS[(t + 1) * BB + bbase + eb];
        const int lane_owner = jq * 8 + (eb >> 2);
        const int rbase = lane_owner * 52 + (eb & 3) * 12;
        float nhv[4];
#pragma unroll
        for (int ii = 0; ii < 4; ++ii) {
            float aR = 0.f, aZ = 0.f, aN = 0.f;
#pragma unroll
            for (int w = 0; w < 4; ++w) {
                const float* p = sRed + w * (32 * 52) + rbase + ii * 3;
                aR += p[0]; aZ += p[1]; aN += p[2];
            }
            const int jl = jq * 4 + ii;
            const float gir = gib[(0 * 32 + eb) * 16 + jl];
            const float giz = gib[(1 * 32 + eb) * 16 + jl];
            const float gin = gib[(2 * 32 + eb) * 16 + jl];
            const float rr = fsigmoid(aR + gir);
            const float zz = fsigmoid(aZ + giz);
            const float nn = ftanh_fast(gin + rr * (aN + bhn_j[ii]));
            nhv[ii] = (1.f - zz) * nn + zz * hv[ii];
        }
        float4 nh4;
        nh4.x = nhv[0]; nh4.y = nhv[1]; nh4.z = nhv[2]; nh4.w = nhv[3];
        *(float4*)(out + ((size_t)t * BB + bbase + eb) * HH + jbase + jq * 4) = nh4;
#pragma unroll
        for (int ii = 0; ii < 4; ++ii)
            hdst[(size_t)(jbase + jq * 4 + ii) * BB + bbase + eb] = nhv[ii] * rs;

        // prefetch gi for step t+1 into the other buffer (hidden behind barrier)
        {
            const int tn = (t + 1 < TT) ? (t + 1) : (TT - 1);
            float* gin_dst = sGI + ((t + 1) & 1) * 1536;
            const float* gin_src = g_GI + (size_t)tn * BB * H3;
#pragma unroll
            for (int q = 0; q < 3; ++q) {
                int p = tid + q * SCAN_THREADS;
                int g = p >> 7, rem = p & 127;
                int b = rem >> 2, j4 = rem & 3;
                cp16(gin_dst + (g * 32 + b) * 16 + j4 * 4,
                     gin_src + (size_t)(bbase + b) * H3 + g * HH + jbase + j4 * 4);
            }
            asm volatile("cp.async.commit_group;");
        }

        group_sync(bi, gen);
    }
}

// ---------------- launch ----------------
extern "C" void kernel_launch(void* const* d_in, const int* in_sizes, int n_in,
                              void* d_out, int out_size) {
    const float* x    = (const float*)d_in[0];   // [T,B,H]
    const void*  rst  = d_in[1];                 // [T,B] bool (unknown storage)
    const float* Wi   = (const float*)d_in[2];   // [H,3H]
    const float* bi   = (const float*)d_in[3];   // [3H]
    const float* Wh   = (const float*)d_in[4];   // [H,3H]
    const float* bhn  = (const float*)d_in[5];   // [H]
    const float* h0   = (const float*)d_in[6];   // [B,H]
    float* out = (float*)d_out;

    (void)in_sizes; (void)n_in; (void)out_size;

    detect_reset_mode_kernel<<<1, 256>>>((const unsigned char*)rst);
    expand_resets_kernel<<<((TT + 1) * BB + 255) / 256, 256>>>(rst);
    init_kernel<<<(BB * HH + 255) / 256, 256>>>(h0);

    // split-fp32 -> bf16 operand build
    convert_x_kernel<<<4096, 256>>>(x);
    convert_w_kernel<<<1024, 256>>>(Wi);

    // GI = x @ Wi + bi via HMMA bf16 (split-K' = 1536)
    cudaFuncSetAttribute(gi_hmma_kernel,
                         cudaFuncAttributeMaxDynamicSharedMemorySize, HB_SMEM_BYTES);
    gi_hmma_kernel<<<6144, 256, HB_SMEM_BYTES>>>(bi);

    // persistent sequential scan
    cudaFuncSetAttribute(scan_kernel,
                         cudaFuncAttributeMaxDynamicSharedMemorySize, SCAN_SMEM_BYTES);
    scan_kernel<<<NCTA, SCAN_THREADS, SCAN_SMEM_BYTES>>>(Wh, bhn, out);
}

// round 12
// speedup vs baseline: 2.7267x; 1.2692x over previous
#include <cuda_runtime.h>
#include <cuda_bf16.h>
#include <math.h>
#include <cstdint>

// Problem sizes (fixed by the reference)
#define TT 512
#define BB 128
#define HH 512
#define H3 1536
#define KP 1536   // GI split-K' = 3*HH

// ---------------- scratch (static __device__, no allocs) ----------------
__device__ float g_GI[TT * BB * H3];                  // x@Wi + bi (fp32)
__device__ __nv_bfloat16 g_A2[(size_t)TT * BB * KP];  // A' = [x_hi | x_lo | x_hi]
__device__ __nv_bfloat16 g_WT[(size_t)H3 * KP];       // Wi'^T for GI GEMM
__device__ __nv_bfloat16 g_Hbf[2 * BB * 1024];        // h state: [buf][b][lo_s 0..511 | hi 512..1023]
__device__ __nv_bfloat16 g_Wbf[(size_t)H3 * 1024];    // Wh rows: [gc][Whi 0..511 | Wlo_s 512..1023]
__device__ float g_RS[(TT + 1) * BB];                 // keep multipliers (0 = reset)
__device__ int   g_reset_mode;
__device__ unsigned int g_cnt[4];                     // per-group barrier counters
__device__ unsigned int g_gen2[4];                    // per-group barrier generations

// ---------------- small PTX helpers ----------------
__device__ __forceinline__ void cp16(void* dst, const void* src) {
    unsigned s = (unsigned)__cvta_generic_to_shared(dst);
    asm volatile("cp.async.cg.shared.global [%0], [%1], 16;" :: "r"(s), "l"(src));
}
__device__ __forceinline__ uint32_t smem_u32(const void* p) {
    return (uint32_t)__cvta_generic_to_shared(p);
}
__device__ __forceinline__ void ldsm_x4(uint32_t& r0, uint32_t& r1,
                                        uint32_t& r2, uint32_t& r3, uint32_t addr) {
    asm volatile("ldmatrix.sync.aligned.m8n8.x4.shared.b16 {%0,%1,%2,%3}, [%4];"
                 : "=r"(r0), "=r"(r1), "=r"(r2), "=r"(r3) : "r"(addr));
}
__device__ __forceinline__ void mma_bf16(float* d, const uint32_t* a,
                                         uint32_t b0, uint32_t b1) {
    asm volatile("mma.sync.aligned.m16n8k16.row.col.f32.bf16.bf16.f32 "
                 "{%0,%1,%2,%3}, {%4,%5,%6,%7}, {%8,%9}, {%0,%1,%2,%3};"
                 : "+f"(d[0]), "+f"(d[1]), "+f"(d[2]), "+f"(d[3])
                 : "r"(a[0]), "r"(a[1]), "r"(a[2]), "r"(a[3]), "r"(b0), "r"(b1));
}
// fast activations: ex2.approx/rcp.approx (rel err ~2^-22), clamped
__device__ __forceinline__ float fsigmoid(float x) {
    x = fminf(30.f, fmaxf(-30.f, x));
    float e;
    asm("ex2.approx.f32 %0, %1;" : "=f"(e) : "f"(-1.4426950408889634f * x));
    float r;
    asm("rcp.approx.f32 %0, %1;" : "=f"(r) : "f"(1.0f + e));
    return r;
}
__device__ __forceinline__ float ftanh_fast(float x) {
    x = fminf(30.f, fmaxf(-30.f, x));
    float e;
    asm("ex2.approx.f32 %0, %1;" : "=f"(e) : "f"(-2.8853900817779268f * x));
    float r;
    asm("rcp.approx.f32 %0, %1;" : "=f"(r) : "f"(1.0f + e));
    return (1.0f - e) * r;
}

// ---------------- detect how the harness stored the bool resets ----------
__global__ void detect_reset_mode_kernel(const unsigned char* __restrict__ r) {
    __shared__ int cnt[4];
    if (threadIdx.x < 4) cnt[threadIdx.x] = 0;
    __syncthreads();
    int local[4] = {0, 0, 0, 0};
    const uchar4* r4 = (const uchar4*)r;
    for (int i = threadIdx.x; i < (TT * BB) / 4; i += blockDim.x) {
        uchar4 v = r4[i];
        local[0] += (v.x != 0); local[1] += (v.y != 0);
        local[2] += (v.z != 0); local[3] += (v.w != 0);
    }
#pragma unroll
    for (int q = 0; q < 4; ++q) atomicAdd(&cnt[q], local[q]);
    __syncthreads();
    if (threadIdx.x == 0) {
        int mode;
        if (cnt[1] > 0) mode = 1;
        else if (cnt[0] > 0) mode = 0;
        else if (cnt[2] > 0 || cnt[3] > 0) mode = 2;
        else mode = 0;
        g_reset_mode = mode;
    }
}

__global__ void expand_resets_kernel(const void* __restrict__ resets) {
    int i = blockIdx.x * blockDim.x + threadIdx.x;
    if (i >= (TT + 1) * BB) return;
    if (i >= TT * BB) { g_RS[i] = 1.0f; return; }
    const int mode = g_reset_mode;
    bool rst;
    if (mode == 0)      rst = ((const int*)resets)[i] != 0;
    else if (mode == 1) rst = ((const unsigned char*)resets)[i] != 0;
    else                rst = ((const float*)resets)[i] != 0.0f;
    g_RS[i] = rst ? 0.0f : 1.0f;
}

// init: barrier state + h0 (reset-applied, bf16 hi/lo split, [b][k'] layout)
__global__ void init_kernel(const float* __restrict__ h0) {
    int i = blockIdx.x * blockDim.x + threadIdx.x;
    if (i < 4) { g_cnt[i] = 0u; g_gen2[i] = 0u; }
    if (i < BB * HH) {
        int b = i >> 9;
        int j = i & (HH - 1);
        float h = h0[i] * g_RS[b];
        __nv_bfloat16 hi = __float2bfloat16(h);
        __nv_bfloat16 lo = __float2bfloat16((h - __bfloat162float(hi)) * 256.0f);
        g_Hbf[b * 1024 + j] = lo;
        g_Hbf[b * 1024 + 512 + j] = hi;
    }
}

// ---------------- split-fp32 -> bf16 conversion kernels ----------------
__global__ void convert_x_kernel(const float* __restrict__ x) {
    const int n = TT * BB * HH;
    for (int idx = blockIdx.x * blockDim.x + threadIdx.x; idx < n;
         idx += gridDim.x * blockDim.x) {
        int m = idx >> 9, k = idx & 511;
        float v = x[idx];
        __nv_bfloat16 hi = __float2bfloat16(v);
        __nv_bfloat16 lo = __float2bfloat16(v - __bfloat162float(hi));
        size_t base = (size_t)m * KP;
        g_A2[base + k] = hi;
        g_A2[base + 512 + k] = lo;
        g_A2[base + 1024 + k] = hi;
    }
}
__global__ void convert_w_kernel(const float* __restrict__ Wi) {
    const int n = HH * H3;
    for (int idx = blockIdx.x * blockDim.x + threadIdx.x; idx < n;
         idx += gridDim.x * blockDim.x) {
        int k = idx / H3, c = idx % H3;          // Wi[k][c]
        float v = Wi[idx];
        __nv_bfloat16 hi = __float2bfloat16(v);
        __nv_bfloat16 lo = __float2bfloat16(v - __bfloat162float(hi));
        size_t base = (size_t)c * KP;
        g_WT[base + k] = hi;
        g_WT[base + 512 + k] = hi;
        g_WT[base + 1024 + k] = lo;
    }
}
// Wh -> g_Wbf rows: [gc][Whi(k) 0..511 | Wlo_s(k) 512..1023]
__global__ void convert_wh_kernel(const float* __restrict__ Wh) {
    const int n = HH * H3;
    for (int idx = blockIdx.x * blockDim.x + threadIdx.x; idx < n;
         idx += gridDim.x * blockDim.x) {
        int gc = idx >> 9, k = idx & 511;
        float v = Wh[(size_t)k * H3 + gc];
        __nv_bfloat16 hi = __float2bfloat16(v);
        __nv_bfloat16 lo = __float2bfloat16((v - __bfloat162float(hi)) * 256.0f);
        g_Wbf[(size_t)gc * 1024 + k] = hi;
        g_Wbf[(size_t)gc * 1024 + 512 + k] = lo;
    }
}

// ---------------- GI GEMM via mma.sync bf16 (HMMA) -----------------------
#define HBM_M 128
#define HBM_N 128
#define HBM_K 32
#define APITCH 40
#define STAGE_BYTES 20480
#define NSTAGE 3
#define HB_BIAS_OFF (NSTAGE * STAGE_BYTES)
#define HB_SMEM_BYTES (HB_BIAS_OFF + 512)
#define NC (KP / HBM_K)

extern __shared__ float smf[];

__device__ __forceinline__ void hmma_stage(char* smc, int slot, int kc,
                                           const __nv_bfloat16* Ag,
                                           const __nv_bfloat16* Bg, int tid) {
    char* sA = smc + slot * STAGE_BYTES;
    char* sB = sA + 10240;
    const int k0 = kc * HBM_K;
#pragma unroll
    for (int i = 0; i < 2; ++i) {
        int id = tid * 2 + i;
        int row = id >> 2, seg = id & 3;
        cp16(sA + row * 80 + seg * 16, Ag + (size_t)row * KP + k0 + seg * 8);
        cp16(sB + row * 80 + seg * 16, Bg + (size_t)row * KP + k0 + seg * 8);
    }
}

__global__ __launch_bounds__(256) void gi_hmma_kernel(const float* __restrict__ bias) {
    char* smc = (char*)smf;
    const uint32_t sbase = smem_u32(smc);
    const int tid = threadIdx.x;
    const int lane = tid & 31, warp = tid >> 5;
    const int wm = warp >> 1, wn = warp & 1;

    const int bid = blockIdx.x;
    const int grp = bid / 96, r = bid % 96;
    const int ntile = r % 12, mtile = grp * 8 + r / 12;
    const int m0 = mtile * HBM_M, n0 = ntile * HBM_N;
    const __nv_bfloat16* Ag = g_A2 + (size_t)m0 * KP;
    const __nv_bfloat16* Bg = g_WT + (size_t)n0 * KP;

    float* bsm = (float*)(smc + HB_BIAS_OFF);
    if (tid < 128) bsm[tid] = bias[n0 + tid];

    float acc[2][8][4];
#pragma unroll
    for (int mt = 0; mt < 2; ++mt)
#pragma unroll
        for (int nt = 0; nt < 8; ++nt)
#pragma unroll
            for (int q = 0; q < 4; ++q) acc[mt][nt][q] = 0.f;

    hmma_stage(smc, 0, 0, Ag, Bg, tid);
    asm volatile("cp.async.commit_group;");
    hmma_stage(smc, 1, 1, Ag, Bg, tid);
    asm volatile("cp.async.commit_group;");

    const int lrow = lane & 15;
    const int lcol8 = (lane >> 4) * 8;

    for (int c = 0; c < NC; ++c) {
        if (c == NC - 1) asm volatile("cp.async.wait_group 0;");
        else             asm volatile("cp.async.wait_group 1;");
        __syncthreads();
        if (c + 2 < NC) {
            hmma_stage(smc, (c + 2) % NSTAGE, c + 2, Ag, Bg, tid);
            asm volatile("cp.async.commit_group;");
        }

        const uint32_t aBase = sbase + (uint32_t)(c % NSTAGE) * STAGE_BYTES;
        const uint32_t bBase = aBase + 10240;

#pragma unroll
        for (int ks = 0; ks < 2; ++ks) {
            const int col = ks * 16 + lcol8;
            uint32_t af[2][4];
#pragma unroll
            for (int mt = 0; mt < 2; ++mt) {
                uint32_t addr = aBase +
                    (uint32_t)((wm * 32 + mt * 16 + lrow) * APITCH + col) * 2;
                ldsm_x4(af[mt][0], af[mt][1], af[mt][2], af[mt][3], addr);
            }
            uint32_t bf[4][4];
#pragma unroll
            for (int ng = 0; ng < 4; ++ng) {
                uint32_t addr = bBase +
                    (uint32_t)((wn * 64 + ng * 16 + lrow) * APITCH + col) * 2;
                ldsm_x4(bf[ng][0], bf[ng][1], bf[ng][2], bf[ng][3], addr);
            }
#pragma unroll
            for (int mt = 0; mt < 2; ++mt)
#pragma unroll
                for (int ng = 0; ng < 4; ++ng) {
                    mma_bf16(acc[mt][ng * 2 + 0], af[mt], bf[ng][0], bf[ng][2]);
                    mma_bf16(acc[mt][ng * 2 + 1], af[mt], bf[ng][1], bf[ng][3]);
                }
        }
        __syncthreads();
    }

    const int ml = lane >> 2;
    const int nl = (lane & 3) * 2;
#pragma unroll
    for (int mt = 0; mt < 2; ++mt) {
        const int mg = m0 + wm * 32 + mt * 16 + ml;
#pragma unroll
        for (int nt = 0; nt < 8; ++nt) {
            const int ncol = wn * 64 + nt * 8 + nl;
            const float b0 = bsm[ncol], b1 = bsm[ncol + 1];
            float2 v0, v1;
            v0.x = acc[mt][nt][0] + b0; v0.y = acc[mt][nt][1] + b1;
            v1.x = acc[mt][nt][2] + b0; v1.y = acc[mt][nt][3] + b1;
            *(float2*)(g_GI + (size_t)mg * H3 + n0 + ncol) = v0;
            *(float2*)(g_GI + (size_t)(mg + 8) * H3 + n0 + ncol) = v1;
        }
    }
}

// ---------------- persistent scan kernel: h@Wh via HMMA -------------------
#define NCTA 128
#define SCAN_THREADS 128
#define ROWB 2064     // bytes per smem row (1024 bf16 + 8 pad)
#define SW_OFF   0
#define SA_OFF   99072                       // 48*2064
#define SGI_OFF  (99072 + 66048)             // + 32*2064 = 165120
#define SRED_OFF (165120 + 12288)            // = 177408
#define SCAN_SMEM_BYTES (177408 + 26624)     // = 204032

__device__ __forceinline__ void group_sync(int bi, unsigned int& gen) {
    __syncthreads();
    if (threadIdx.x == 0) {
        unsigned int prev;
        asm volatile("atom.acq_rel.gpu.add.u32 %0, [%1], 1;"
                     : "=r"(prev) : "l"(&g_cnt[bi]) : "memory");
        if (prev == 31u) {
            asm volatile("st.relaxed.gpu.u32 [%0], 0;" :: "l"(&g_cnt[bi]) : "memory");
            unsigned int d;
            asm volatile("atom.release.gpu.add.u32 %0, [%1], 1;"
                         : "=r"(d) : "l"(&g_gen2[bi]) : "memory");
        } else {
            unsigned int cur;
            do {
                asm volatile("ld.acquire.gpu.u32 %0, [%1];"
                             : "=r"(cur) : "l"(&g_gen2[bi]) : "memory");
            } while (cur == gen);
        }
    }
    gen++;
    __syncthreads();
}

__global__ __launch_bounds__(SCAN_THREADS, 1) void scan_kernel(
    const float* __restrict__ bhn,             // [H]
    float* __restrict__ out)                   // [T,B,H]
{
    char* smc = (char*)smf;
    char* sW  = smc + SW_OFF;                  // 48 rows x 2064B: [c][Whi|Wlo_s]
    char* sA  = smc + SA_OFF;                  // 32 rows x 2064B: [b][lo_s|hi]
    float* sGI  = (float*)(smc + SGI_OFF);     // [2][3][32][16]
    float* sRed = (float*)(smc + SRED_OFF);    // [4][32][52]
    const uint32_t sWu = smem_u32(sW);
    const uint32_t sAu = smem_u32(sA);

    const int tid  = threadIdx.x;
    const int lane = tid & 31;
    const int wid  = tid >> 5;
    const int ji   = blockIdx.x & 31;
    const int bi   = blockIdx.x >> 5;
    const int jbase = ji * 16;
    const int bbase = bi * 32;
    const int eb = tid & 31;
    const int jq = tid >> 5;

    // stage weights once: 48 rows of 2048B
    for (int p = tid; p < 48 * 128; p += SCAN_THREADS) {
        int row = p >> 7, seg = p & 127;
        int gc = (row % 3) * HH + jbase + row / 3;   // c = jl*3+g -> gc
        cp16(sW + row * ROWB + seg * 16, g_Wbf + (size_t)gc * 1024 + seg * 8);
    }
    // prefetch gi for t=0 into buffer 0
#pragma unroll
    for (int q = 0; q < 3; ++q) {
        int p = tid + q * SCAN_THREADS;
        int g = p >> 7, rem = p & 127;
        int b = rem >> 2, j4 = rem & 3;
        cp16(sGI + (g * 32 + b) * 16 + j4 * 4,
             g_GI + (size_t)(bbase + b) * H3 + g * HH + jbase + j4 * 4);
    }
    asm volatile("cp.async.commit_group;");

    float bhn_j[4];
#pragma unroll
    for (int ii = 0; ii < 4; ++ii) bhn_j[ii] = bhn[jbase + jq * 4 + ii];

    const int lrow = lane & 15;
    const int lcol8 = (lane >> 4) * 8;
    unsigned int gen = 0;

    for (int t = 0; t < TT; ++t) {
        const __nv_bfloat16* hsrc = g_Hbf + (t & 1) * BB * 1024;
        __nv_bfloat16* hdst       = g_Hbf + ((t + 1) & 1) * BB * 1024;

        // stage h slice: 32 rows x 2048B
#pragma unroll
        for (int q = 0; q < 32; ++q) {
            int p = tid + q * SCAN_THREADS;
            int row = p >> 7, seg = p & 127;
            cp16(sA + row * ROWB + seg * 16,
                 hsrc + (size_t)(bbase + row) * 1024 + seg * 8);
        }
        asm volatile("cp.async.commit_group;");
        asm volatile("cp.async.wait_group 0;");
        __syncthreads();

        float acc1[2][6][4], acc2[2][6][4];
#pragma unroll
        for (int mt = 0; mt < 2; ++mt)
#pragma unroll
            for (int nt = 0; nt < 6; ++nt)
#pragma unroll
                for (int q = 0; q < 4; ++q) { acc1[mt][nt][q] = 0.f; acc2[mt][nt][q] = 0.f; }

        // acc1: hi @ Whi.  A k' in [512 + wid*128, +128), B k in [wid*128, +128)
#pragma unroll
        for (int ks = 0; ks < 8; ++ks) {
            const int colA = 512 + wid * 128 + ks * 16 + lcol8;
            const int colB = wid * 128 + ks * 16 + lcol8;
            uint32_t af[2][4];
#pragma unroll
            for (int mt = 0; mt < 2; ++mt)
                ldsm_x4(af[mt][0], af[mt][1], af[mt][2], af[mt][3],
                        sAu + (uint32_t)(mt * 16 + lrow) * ROWB + colA * 2);
            uint32_t bf[3][4];
#pragma unroll
            for (int ng = 0; ng < 3; ++ng)
                ldsm_x4(bf[ng][0], bf[ng][1], bf[ng][2], bf[ng][3],
                        sWu + (uint32_t)(ng * 16 + lrow) * ROWB + colB * 2);
#pragma unroll
            for (int mt = 0; mt < 2; ++mt)
#pragma unroll
                for (int ng = 0; ng < 3; ++ng) {
                    mma_bf16(acc1[mt][ng * 2 + 0], af[mt], bf[ng][0], bf[ng][2]);
                    mma_bf16(acc1[mt][ng * 2 + 1], af[mt], bf[ng][1], bf[ng][3]);
                }
        }
        // acc2: [lo_s | hi] @ [Whi ; Wlo_s].  k' in [wid*256, +256), same for A and B
#pragma unroll
        for (int ks = 0; ks < 16; ++ks) {
            const int col = wid * 256 + ks * 16 + lcol8;
            uint32_t af[2][4];
#pragma unroll
            for (int mt = 0; mt < 2; ++mt)
                ldsm_x4(af[mt][0], af[mt][1], af[mt][2], af[mt][3],
                        sAu + (uint32_t)(mt * 16 + lrow) * ROWB + col * 2);
            uint32_t bf[3][4];
#pragma unroll
            for (int ng = 0; ng < 3; ++ng)
                ldsm_x4(bf[ng][0], bf[ng][1], bf[ng][2], bf[ng][3],
                        sWu + (uint32_t)(ng * 16 + lrow) * ROWB + col * 2);
#pragma unroll
            for (int mt = 0; mt < 2; ++mt)
#pragma unroll
                for (int ng = 0; ng < 3; ++ng) {
                    mma_bf16(acc2[mt][ng * 2 + 0], af[mt], bf[ng][0], bf[ng][2]);
                    mma_bf16(acc2[mt][ng * 2 + 1], af[mt], bf[ng][1], bf[ng][3]);
                }
        }

        // combine + write per-warp partials to sRed[w][b][c]
        {
            const int bfr = lane >> 2;
            const int cfr = (lane & 3) * 2;
            float* rw = sRed + wid * (32 * 52);
#pragma unroll
            for (int mt = 0; mt < 2; ++mt)
#pragma unroll
                for (int nt = 0; nt < 6; ++nt) {
                    const int b0 = mt * 16 + bfr;
                    const int c0 = nt * 8 + cfr;
                    float2 v0, v1;
                    v0.x = acc1[mt][nt][0] + acc2[mt][nt][0] * 0.00390625f;
                    v0.y = acc1[mt][nt][1] + acc2[mt][nt][1] * 0.00390625f;
                    v1.x = acc1[mt][nt][2] + acc2[mt][nt][2] * 0.00390625f;
                    v1.y = acc1[mt][nt][3] + acc2[mt][nt][3] * 0.00390625f;
                    *(float2*)(rw + b0 * 52 + c0) = v0;
                    *(float2*)(rw + (b0 + 8) * 52 + c0) = v1;
                }
        }

        // old-h for the z-blend, reconstructed exactly from staged hi/lo
        float hv[4];
        {
            const __nv_bfloat16* sAb = (const __nv_bfloat16*)sA;
#pragma unroll
            for (int ii = 0; ii < 4; ++ii) {
                const int jg = jbase + jq * 4 + ii;
                float hi = __bfloat162float(sAb[eb * 1032 + 512 + jg]);
                float lo = __bfloat162float(sAb[eb * 1032 + jg]);
                hv[ii] = hi + lo * 0.00390625f;
            }
        }
        __syncthreads();

        // epilogue: thread handles (b = bbase+eb, j = jbase + jq*4 + ii)
        const float* gib = sGI + (t & 1) * 1536;
        const float rs = g_RS[(t + 1) * BB + bbase + eb];
        float nhv[4];
#pragma unroll
        for (int ii = 0; ii < 4; ++ii) {
            const int cb = (jq * 4 + ii) * 3;
            float aR = 0.f, aZ = 0.f, aN = 0.f;
#pragma unroll
            for (int w = 0; w < 4; ++w) {
                const float* p = sRed + w * (32 * 52) + eb * 52 + cb;
                aR += p[0]; aZ += p[1]; aN += p[2];
            }
            const int jl = jq * 4 + ii;
            const float gir = gib[(0 * 32 + eb) * 16 + jl];
            const float giz = gib[(1 * 32 + eb) * 16 + jl];
            const float gin = gib[(2 * 32 + eb) * 16 + jl];
            const float rr = fsigmoid(aR + gir);
            const float zz = fsigmoid(aZ + giz);
            const float nn = ftanh_fast(gin + rr * (aN + bhn_j[ii]));
            nhv[ii] = (1.f - zz) * nn + zz * hv[ii];
        }
        float4 nh4;
        nh4.x = nhv[0]; nh4.y = nhv[1]; nh4.z = nhv[2]; nh4.w = nhv[3];
        *(float4*)(out + ((size_t)t * BB + bbase + eb) * HH + jbase + jq * 4) = nh4;

        // store next h (reset folded) as bf16 hi/lo, row-major [b][k']
        {
            union { __nv_bfloat16 b[4]; unsigned long long u; } phi, plo;
#pragma unroll
            for (int ii = 0; ii < 4; ++ii) {
                float hn = nhv[ii] * rs;
                __nv_bfloat16 hi = __float2bfloat16(hn);
                __nv_bfloat16 lo = __float2bfloat16((hn - __bfloat162float(hi)) * 256.0f);
                phi.b[ii] = hi; plo.b[ii] = lo;
            }
            const size_t rowb = (size_t)(bbase + eb) * 1024 + jbase + jq * 4;
            *(unsigned long long*)(hdst + rowb) = plo.u;
            *(unsigned long long*)(hdst + rowb + 512) = phi.u;
        }

        // prefetch gi for step t+1
        {
            const int tn = (t + 1 < TT) ? (t + 1) : (TT - 1);
            float* gin_dst = sGI + ((t + 1) & 1) * 1536;
            const float* gin_src = g_GI + (size_t)tn * BB * H3;
#pragma unroll
            for (int q = 0; q < 3; ++q) {
                int p = tid + q * SCAN_THREADS;
                int g = p >> 7, rem = p & 127;
                int b = rem >> 2, j4 = rem & 3;
                cp16(gin_dst + (g * 32 + b) * 16 + j4 * 4,
                     gin_src + (size_t)(bbase + b) * H3 + g * HH + jbase + j4 * 4);
            }
            asm volatile("cp.async.commit_group;");
        }

        group_sync(bi, gen);
    }
}

// ---------------- launch ----------------
extern "C" void kernel_launch(void* const* d_in, const int* in_sizes, int n_in,
                              void* d_out, int out_size) {
    const float* x    = (const float*)d_in[0];   // [T,B,H]
    const void*  rst  = d_in[1];                 // [T,B] bool (unknown storage)
    const float* Wi   = (const float*)d_in[2];   // [H,3H]
    const float* bi   = (const float*)d_in[3];   // [3H]
    const float* Wh   = (const float*)d_in[4];   // [H,3H]
    const float* bhn  = (const float*)d_in[5];   // [H]
    const float* h0   = (const float*)d_in[6];   // [B,H]
    float* out = (float*)d_out;

    (void)in_sizes; (void)n_in; (void)out_size;

    detect_reset_mode_kernel<<<1, 256>>>((const unsigned char*)rst);
    expand_resets_kernel<<<((TT + 1) * BB + 255) / 256, 256>>>(rst);
    init_kernel<<<(BB * HH + 255) / 256, 256>>>(h0);

    // bf16 operand builds
    convert_x_kernel<<<4096, 256>>>(x);
    convert_w_kernel<<<1024, 256>>>(Wi);
    convert_wh_kernel<<<1024, 256>>>(Wh);

    // GI = x @ Wi + bi via HMMA bf16
    cudaFuncSetAttribute(gi_hmma_kernel,
                         cudaFuncAttributeMaxDynamicSharedMemorySize, HB_SMEM_BYTES);
    gi_hmma_kernel<<<6144, 256, HB_SMEM_BYTES>>>(bi);

    // persistent sequential scan (h@Wh on tensor pipe)
    cudaFuncSetAttribute(scan_kernel,
                         cudaFuncAttributeMaxDynamicSharedMemorySize, SCAN_SMEM_BYTES);
    scan_kernel<<<NCTA, SCAN_THREADS, SCAN_SMEM_BYTES>>>(bhn, out);
}